// round 1
// baseline (speedup 1.0000x reference)
#include <cuda_runtime.h>
#include <math.h>

#define SEQ   1024
#define BATCH 4
#define DM    1024
#define NH    16
#define HD    64
#define NPOS  1000
#define NTOK  (SEQ*BATCH)   // 4096
#define TS    8             // s-rows per attention block

// Scratch (device globals; no runtime allocation allowed)
__device__ float g_q[NH*BATCH*SEQ*HD];
__device__ float g_k[NH*BATCH*SEQ*HD];
__device__ float g_v[NH*BATCH*SEQ*HD];
__device__ float g_ctx[NTOK*DM];

// ---------------------------------------------------------------------------
// QKV projection GEMM: out(m,n) = x(m,:)·W(:,n) + b(n), scattered to
// head layout q[((h*B+b)*S + s)*64 + d],  h=n/64, d=n%64, s=m/B, b=m%B.
// 64x64 tile, K-tile 16, 256 threads, 4x4 per thread.
// ---------------------------------------------------------------------------
__global__ __launch_bounds__(256) void qkv_gemm(
    const float* __restrict__ x,
    const float* __restrict__ Wq, const float* __restrict__ bq,
    const float* __restrict__ Wk, const float* __restrict__ bk,
    const float* __restrict__ Wv, const float* __restrict__ bv)
{
    const float* W;  const float* bias;  float* out;
    if (blockIdx.z == 0)      { W = Wq; bias = bq; out = g_q; }
    else if (blockIdx.z == 1) { W = Wk; bias = bk; out = g_k; }
    else                      { W = Wv; bias = bv; out = g_v; }

    __shared__ float As[16][68];
    __shared__ float Bs[16][68];

    int m0 = blockIdx.y * 64;
    int n0 = blockIdx.x * 64;
    int tid = threadIdx.x;
    int tx = tid & 15, ty = tid >> 4;

    float acc[4][4] = {};

    for (int k0 = 0; k0 < DM; k0 += 16) {
        // A tile: 64 rows x 16 cols (transposed into As[k][m])
        {
            int row = tid >> 2;          // 0..63
            int cg  = (tid & 3) * 4;     // 0,4,8,12
            float4 a = *(const float4*)(x + (size_t)(m0 + row) * DM + k0 + cg);
            As[cg + 0][row] = a.x; As[cg + 1][row] = a.y;
            As[cg + 2][row] = a.z; As[cg + 3][row] = a.w;
        }
        // B tile: 16 rows x 64 cols
        {
            int kr = tid >> 4;           // 0..15
            int cg = (tid & 15) * 4;     // 0..60
            float4 b = *(const float4*)(W + (size_t)(k0 + kr) * DM + n0 + cg);
            Bs[kr][cg + 0] = b.x; Bs[kr][cg + 1] = b.y;
            Bs[kr][cg + 2] = b.z; Bs[kr][cg + 3] = b.w;
        }
        __syncthreads();
        #pragma unroll
        for (int kk = 0; kk < 16; kk++) {
            float a[4], b[4];
            #pragma unroll
            for (int i = 0; i < 4; i++) a[i] = As[kk][ty * 4 + i];
            #pragma unroll
            for (int j = 0; j < 4; j++) b[j] = Bs[kk][tx * 4 + j];
            #pragma unroll
            for (int i = 0; i < 4; i++)
                #pragma unroll
                for (int j = 0; j < 4; j++)
                    acc[i][j] += a[i] * b[j];
        }
        __syncthreads();
    }

    #pragma unroll
    for (int i = 0; i < 4; i++) {
        int m = m0 + ty * 4 + i;
        int s = m >> 2;       // m / BATCH
        int b_ = m & 3;       // m % BATCH
        #pragma unroll
        for (int j = 0; j < 4; j++) {
            int n = n0 + tx * 4 + j;
            int h = n >> 6, d = n & 63;
            out[((size_t)(h * BATCH + b_) * SEQ + s) * HD + d] = acc[i][j] + bias[n];
        }
    }
}

// ---------------------------------------------------------------------------
// Output projection GEMM: d_out(m,n) = ctx(m,:)·Wo(:,n) + bo(n)
// ---------------------------------------------------------------------------
__global__ __launch_bounds__(256) void out_gemm(
    const float* __restrict__ Wo, const float* __restrict__ bo,
    float* __restrict__ out)
{
    __shared__ float As[16][68];
    __shared__ float Bs[16][68];

    int m0 = blockIdx.y * 64;
    int n0 = blockIdx.x * 64;
    int tid = threadIdx.x;
    int tx = tid & 15, ty = tid >> 4;

    float acc[4][4] = {};

    for (int k0 = 0; k0 < DM; k0 += 16) {
        {
            int row = tid >> 2;
            int cg  = (tid & 3) * 4;
            float4 a = *(const float4*)(g_ctx + (size_t)(m0 + row) * DM + k0 + cg);
            As[cg + 0][row] = a.x; As[cg + 1][row] = a.y;
            As[cg + 2][row] = a.z; As[cg + 3][row] = a.w;
        }
        {
            int kr = tid >> 4;
            int cg = (tid & 15) * 4;
            float4 b = *(const float4*)(Wo + (size_t)(k0 + kr) * DM + n0 + cg);
            Bs[kr][cg + 0] = b.x; Bs[kr][cg + 1] = b.y;
            Bs[kr][cg + 2] = b.z; Bs[kr][cg + 3] = b.w;
        }
        __syncthreads();
        #pragma unroll
        for (int kk = 0; kk < 16; kk++) {
            float a[4], b[4];
            #pragma unroll
            for (int i = 0; i < 4; i++) a[i] = As[kk][ty * 4 + i];
            #pragma unroll
            for (int j = 0; j < 4; j++) b[j] = Bs[kk][tx * 4 + j];
            #pragma unroll
            for (int i = 0; i < 4; i++)
                #pragma unroll
                for (int j = 0; j < 4; j++)
                    acc[i][j] += a[i] * b[j];
        }
        __syncthreads();
    }

    #pragma unroll
    for (int i = 0; i < 4; i++) {
        int m = m0 + ty * 4 + i;
        #pragma unroll
        for (int j = 0; j < 4; j++) {
            int n = n0 + tx * 4 + j;
            out[(size_t)m * DM + n] = acc[i][j] + bo[n];
        }
    }
}

// ---------------------------------------------------------------------------
// Fused CoPE attention per (h, b, 8 s-rows).
// SMEM layout (dynamic, floats):
//   s_log : [TS*1024]  attn logits -> attn weights
//   s_li  : [TS*1024]  interpolation logits q·pos_emb (stride 1024, 1000 valid)
//   s_aux : [TS*1024]  k/pe/v tile (pitch 65) OR pos matrix
//   s_q   : [TS*64]
//   s_red : [8]
// ---------------------------------------------------------------------------
__device__ __forceinline__ float sigmoidf_(float x) {
    return 1.0f / (1.0f + __expf(-x));
}

__global__ __launch_bounds__(256) void cope_attn(const float* __restrict__ pe,
                                                 float* __restrict__ ctx)
{
    extern __shared__ float sm[];
    float* s_log = sm;
    float* s_li  = sm + TS * 1024;
    float* s_aux = sm + 2 * TS * 1024;
    float* s_q   = sm + 3 * TS * 1024;
    float* s_red = s_q + TS * HD;

    int tid = threadIdx.x;
    int bid = blockIdx.x;
    const int nst = SEQ / TS;          // 128
    int hb = bid / nst;                // h*BATCH + b, 0..63
    int s0 = (bid % nst) * TS;
    int h = hb >> 2;
    int b = hb & 3;

    const float* qb = g_q + (size_t)hb * SEQ * HD;
    const float* kb = g_k + (size_t)hb * SEQ * HD;
    const float* vb = g_v + (size_t)hb * SEQ * HD;

    // Load q rows (contiguous)
    for (int l = tid; l < TS * HD; l += 256)
        s_q[l] = qb[(size_t)s0 * HD + l];
    __syncthreads();

    const float scale = 0.125f;  // 1/sqrt(64)

    // ---------------- Phase A: logits = scale * q k^T ----------------
    for (int t0 = 0; t0 < SEQ; t0 += 64) {
        for (int l = tid; l < 64 * 16; l += 256) {
            int row = l >> 4, cg = (l & 15) * 4;
            float4 kv = *(const float4*)(kb + (size_t)(t0 + row) * HD + cg);
            float* dst = s_aux + row * 65 + cg;
            dst[0] = kv.x; dst[1] = kv.y; dst[2] = kv.z; dst[3] = kv.w;
        }
        __syncthreads();
        int tl = tid & 63, rr = tid >> 6;
        #pragma unroll
        for (int rp = 0; rp < 2; rp++) {
            int r = rr * 2 + rp;
            const float* qr = s_q + r * HD;
            const float* kr = s_aux + tl * 65;
            float acc = 0.f;
            #pragma unroll
            for (int d = 0; d < HD; d++) acc += qr[d] * kr[d];
            s_log[r * 1024 + t0 + tl] = acc * scale;
        }
        __syncthreads();
    }

    // ---------------- Phase C: li[n] = q · pos_emb[:,n] ----------------
    for (int n0 = 0; n0 < 1024; n0 += 64) {
        for (int l = tid; l < 64 * 16; l += 256) {
            int d = l >> 4, cg = (l & 15) * 4;
            float v0 = 0.f, v1 = 0.f, v2 = 0.f, v3 = 0.f;
            int base = n0 + cg;
            if (base + 3 < NPOS) {
                float4 pv = *(const float4*)(pe + (size_t)d * NPOS + base);
                v0 = pv.x; v1 = pv.y; v2 = pv.z; v3 = pv.w;
            } else {
                if (base + 0 < NPOS) v0 = pe[(size_t)d * NPOS + base + 0];
                if (base + 1 < NPOS) v1 = pe[(size_t)d * NPOS + base + 1];
                if (base + 2 < NPOS) v2 = pe[(size_t)d * NPOS + base + 2];
                if (base + 3 < NPOS) v3 = pe[(size_t)d * NPOS + base + 3];
            }
            float* dst = s_aux + d * 65 + cg;
            dst[0] = v0; dst[1] = v1; dst[2] = v2; dst[3] = v3;
        }
        __syncthreads();
        int nl = tid & 63, rr = tid >> 6;
        #pragma unroll
        for (int rp = 0; rp < 2; rp++) {
            int r = rr * 2 + rp;
            const float* qr = s_q + r * HD;
            float acc = 0.f;
            #pragma unroll
            for (int d = 0; d < HD; d++) acc += qr[d] * s_aux[d * 65 + nl];
            s_li[r * 1024 + n0 + nl] = acc;
        }
        __syncthreads();
    }

    // ---------------- Phase B: pos = clamp(rev-cumsum(sigmoid(logits))) ------
    {
        int lane = tid & 31, warp = tid >> 5;
        for (int r = 0; r < TS; r++) {
            const float* L = s_log + r * 1024;
            float* P = s_aux + r * 1024;
            float4 lv = *(const float4*)(L + tid * 4);
            float g0 = sigmoidf_(lv.x), g1 = sigmoidf_(lv.y);
            float g2 = sigmoidf_(lv.z), g3 = sigmoidf_(lv.w);
            float su3 = g3;
            float su2 = g2 + su3;
            float su1 = g1 + su2;
            float su0 = g0 + su1;        // inclusive suffix within quad
            float chunk = su0;
            // inclusive suffix scan over lanes in warp
            float v = chunk;
            #pragma unroll
            for (int off = 1; off < 32; off <<= 1) {
                float n = __shfl_down_sync(0xffffffffu, v, off);
                if (lane < 32 - off) v += n;
            }
            if (lane == 0) s_red[warp] = v;   // warp suffix totals
            __syncthreads();
            float wsuf = 0.f;
            for (int w = warp + 1; w < 8; w++) wsuf += s_red[w];
            float excl = wsuf + (v - chunk);  // suffix sum over quads after this one
            float p0 = fminf(excl + su0, 999.f);
            float p1 = fminf(excl + su1, 999.f);
            float p2 = fminf(excl + su2, 999.f);
            float p3 = fminf(excl + su3, 999.f);
            float4 pv = make_float4(p0, p1, p2, p3);
            *(float4*)(P + tid * 4) = pv;
            __syncthreads();
        }
    }

    // ---------------- Phase D: logits += interp(li, pos) ----------------
    for (int idx = tid; idx < TS * 1024; idx += 256) {
        int r = idx >> 10;
        float p = s_aux[idx];
        float pf = floorf(p);
        float w = p - pf;
        int fi = (int)pf;
        int ci = (int)ceilf(p);
        const float* lir = s_li + r * 1024;
        float cope = lir[ci] * w + lir[fi] * (1.0f - w);
        s_log[idx] += cope;
    }
    __syncthreads();

    // ---------------- Phase E: softmax (warp per row) ----------------
    {
        int lane = tid & 31, warp = tid >> 5;
        float* L = s_log + warp * 1024;
        float m = -INFINITY;
        for (int j = lane; j < 1024; j += 32) m = fmaxf(m, L[j]);
        #pragma unroll
        for (int off = 16; off; off >>= 1)
            m = fmaxf(m, __shfl_xor_sync(0xffffffffu, m, off));
        float sum = 0.f;
        for (int j = lane; j < 1024; j += 32) {
            float e = __expf(L[j] - m);
            L[j] = e;
            sum += e;
        }
        #pragma unroll
        for (int off = 16; off; off >>= 1)
            sum += __shfl_xor_sync(0xffffffffu, sum, off);
        float inv = 1.0f / sum;
        for (int j = lane; j < 1024; j += 32) L[j] *= inv;
    }
    __syncthreads();

    // ---------------- Phase F: out = attn · v ----------------
    {
        int dl = tid & 63, rr = tid >> 6;   // rows rr and rr+4
        float acc0 = 0.f, acc1 = 0.f;
        for (int t0 = 0; t0 < SEQ; t0 += 64) {
            for (int l = tid; l < 64 * 16; l += 256) {
                int row = l >> 4, cg = (l & 15) * 4;
                float4 vv = *(const float4*)(vb + (size_t)(t0 + row) * HD + cg);
                float* dst = s_aux + row * 65 + cg;
                dst[0] = vv.x; dst[1] = vv.y; dst[2] = vv.z; dst[3] = vv.w;
            }
            __syncthreads();
            const float* a0 = s_log + rr * 1024 + t0;
            const float* a1 = s_log + (rr + 4) * 1024 + t0;
            #pragma unroll
            for (int t = 0; t < 64; t++) {
                float v = s_aux[t * 65 + dl];
                acc0 += a0[t] * v;
                acc1 += a1[t] * v;
            }
            __syncthreads();
        }
        int sa = s0 + rr, sb = s0 + rr + 4;
        ctx[((size_t)sa * BATCH + b) * DM + h * HD + dl] = acc0;
        ctx[((size_t)sb * BATCH + b) * DM + h * HD + dl] = acc1;
    }
}

// ---------------------------------------------------------------------------
extern "C" void kernel_launch(void* const* d_in, const int* in_sizes, int n_in,
                              void* d_out, int out_size)
{
    const float* x  = (const float*)d_in[0];
    const float* Wq = (const float*)d_in[1];
    const float* bq = (const float*)d_in[2];
    const float* Wk = (const float*)d_in[3];
    const float* bk = (const float*)d_in[4];
    const float* Wv = (const float*)d_in[5];
    const float* bv = (const float*)d_in[6];
    const float* Wo = (const float*)d_in[7];
    const float* bo = (const float*)d_in[8];
    const float* pe = (const float*)d_in[9];
    float* out = (float*)d_out;

    const int smem_bytes = (3 * TS * 1024 + TS * HD + 8) * sizeof(float); // 100384
    cudaFuncSetAttribute(cope_attn, cudaFuncAttributeMaxDynamicSharedMemorySize,
                         smem_bytes);

    float* ctx;
    cudaGetSymbolAddress((void**)&ctx, g_ctx);

    dim3 gqkv(DM / 64, NTOK / 64, 3);
    qkv_gemm<<<gqkv, 256>>>(x, Wq, bq, Wk, bk, Wv, bv);

    cope_attn<<<NH * BATCH * (SEQ / TS), 256, smem_bytes>>>(pe, ctx);

    dim3 gout(DM / 64, NTOK / 64);
    out_gemm<<<gout, 256>>>(Wo, bo, out);
}

// round 2
// speedup vs baseline: 1.2839x; 1.2839x over previous
#include <cuda_runtime.h>
#include <math.h>

#define SEQ   1024
#define BATCH 4
#define DM    1024
#define NH    16
#define HD    64
#define NPOS  1000
#define NTOK  (SEQ*BATCH)   // 4096
#define TS    16            // s-rows per attention block
#define CHUNK 256

// SMEM layout for cope_attn (float offsets)
#define KTP 258             // transposed k-tile pitch
#define PEP 260             // pe tile pitch
#define ATP 20              // attnT pitch (1024 x 16, padded)
#define VTP 68              // v tile pitch
#define OFF_LOG 0                    // 16*1024 = 16384
#define OFF_LI  16384                // 16384 (li), later attnT 1024*20=20480 (ends 36864)
#define OFF_AUX 36864                // kt(16512)/pet(16640)/pos(16384)/vt(8704)/red(4096)
#define AUX_SZ  16640
#define OFF_QT  (OFF_AUX + AUX_SZ)   // 53504, size 1024
#define SM_FLOATS (OFF_QT + 1024)    // 54528 floats = 218112 bytes

typedef unsigned long long u64;

__device__ __forceinline__ u64 ffma2(u64 a, u64 b, u64 c) {
    u64 d;
    asm("fma.rn.f32x2 %0, %1, %2, %3;" : "=l"(d) : "l"(a), "l"(b), "l"(c));
    return d;
}
__device__ __forceinline__ u64 pack2(float x, float y) {
    u64 d;
    asm("mov.b64 %0, {%1, %2};" : "=l"(d) : "f"(x), "f"(y));
    return d;
}
__device__ __forceinline__ float2 unpack2(u64 d) {
    float2 r;
    asm("mov.b64 {%0, %1}, %2;" : "=f"(r.x), "=f"(r.y) : "l"(d));
    return r;
}
__device__ __forceinline__ float sigmoidf_(float x) {
    return 1.0f / (1.0f + __expf(-x));
}

// Scratch (device globals; no runtime allocation allowed)
__device__ float g_q[NH*BATCH*SEQ*HD];
__device__ float g_k[NH*BATCH*SEQ*HD];
__device__ float g_v[NH*BATCH*SEQ*HD];
__device__ float g_ctx[NTOK*DM];

// ---------------------------------------------------------------------------
// QKV projection GEMM (f32x2 inner loop), scattered to head layout.
// ---------------------------------------------------------------------------
__global__ __launch_bounds__(256) void qkv_gemm(
    const float* __restrict__ x,
    const float* __restrict__ Wq, const float* __restrict__ bq,
    const float* __restrict__ Wk, const float* __restrict__ bk,
    const float* __restrict__ Wv, const float* __restrict__ bv)
{
    const float* W;  const float* bias;  float* out;
    if (blockIdx.z == 0)      { W = Wq; bias = bq; out = g_q; }
    else if (blockIdx.z == 1) { W = Wk; bias = bk; out = g_k; }
    else                      { W = Wv; bias = bv; out = g_v; }

    __shared__ __align__(16) float As[16][68];
    __shared__ __align__(16) float Bs[16][68];

    int m0 = blockIdx.y * 64;
    int n0 = blockIdx.x * 64;
    int tid = threadIdx.x;
    int tx = tid & 15, ty = tid >> 4;

    u64 acc2[2][4] = {};

    for (int k0 = 0; k0 < DM; k0 += 16) {
        {
            int row = tid >> 2;
            int cg  = (tid & 3) * 4;
            float4 a = *(const float4*)(x + (size_t)(m0 + row) * DM + k0 + cg);
            As[cg + 0][row] = a.x; As[cg + 1][row] = a.y;
            As[cg + 2][row] = a.z; As[cg + 3][row] = a.w;
        }
        {
            int kr = tid >> 4;
            int cg = (tid & 15) * 4;
            float4 b = *(const float4*)(W + (size_t)(k0 + kr) * DM + n0 + cg);
            Bs[kr][cg + 0] = b.x; Bs[kr][cg + 1] = b.y;
            Bs[kr][cg + 2] = b.z; Bs[kr][cg + 3] = b.w;
        }
        __syncthreads();
        #pragma unroll
        for (int kk = 0; kk < 16; kk++) {
            ulonglong2 av = *(const ulonglong2*)&As[kk][ty * 4];
            float4 bv = *(const float4*)&Bs[kk][tx * 4];
            u64 b0 = pack2(bv.x, bv.x), b1 = pack2(bv.y, bv.y);
            u64 b2 = pack2(bv.z, bv.z), b3 = pack2(bv.w, bv.w);
            acc2[0][0] = ffma2(av.x, b0, acc2[0][0]);
            acc2[0][1] = ffma2(av.x, b1, acc2[0][1]);
            acc2[0][2] = ffma2(av.x, b2, acc2[0][2]);
            acc2[0][3] = ffma2(av.x, b3, acc2[0][3]);
            acc2[1][0] = ffma2(av.y, b0, acc2[1][0]);
            acc2[1][1] = ffma2(av.y, b1, acc2[1][1]);
            acc2[1][2] = ffma2(av.y, b2, acc2[1][2]);
            acc2[1][3] = ffma2(av.y, b3, acc2[1][3]);
        }
        __syncthreads();
    }

    #pragma unroll
    for (int ip = 0; ip < 2; ip++) {
        #pragma unroll
        for (int j = 0; j < 4; j++) {
            float2 v = unpack2(acc2[ip][j]);
            int n = n0 + tx * 4 + j;
            int hh = n >> 6, d = n & 63;
            float bb = bias[n];
            int m = m0 + ty * 4 + ip * 2;
            int s = m >> 2, b_ = m & 3;
            out[((size_t)(hh * BATCH + b_) * SEQ + s) * HD + d] = v.x + bb;
            m++; s = m >> 2; b_ = m & 3;
            out[((size_t)(hh * BATCH + b_) * SEQ + s) * HD + d] = v.y + bb;
        }
    }
}

// ---------------------------------------------------------------------------
// Output projection GEMM (f32x2 inner loop)
// ---------------------------------------------------------------------------
__global__ __launch_bounds__(256) void out_gemm(
    const float* __restrict__ Wo, const float* __restrict__ bo,
    float* __restrict__ out)
{
    __shared__ __align__(16) float As[16][68];
    __shared__ __align__(16) float Bs[16][68];

    int m0 = blockIdx.y * 64;
    int n0 = blockIdx.x * 64;
    int tid = threadIdx.x;
    int tx = tid & 15, ty = tid >> 4;

    u64 acc2[2][4] = {};

    for (int k0 = 0; k0 < DM; k0 += 16) {
        {
            int row = tid >> 2;
            int cg  = (tid & 3) * 4;
            float4 a = *(const float4*)(g_ctx + (size_t)(m0 + row) * DM + k0 + cg);
            As[cg + 0][row] = a.x; As[cg + 1][row] = a.y;
            As[cg + 2][row] = a.z; As[cg + 3][row] = a.w;
        }
        {
            int kr = tid >> 4;
            int cg = (tid & 15) * 4;
            float4 b = *(const float4*)(Wo + (size_t)(k0 + kr) * DM + n0 + cg);
            Bs[kr][cg + 0] = b.x; Bs[kr][cg + 1] = b.y;
            Bs[kr][cg + 2] = b.z; Bs[kr][cg + 3] = b.w;
        }
        __syncthreads();
        #pragma unroll
        for (int kk = 0; kk < 16; kk++) {
            ulonglong2 av = *(const ulonglong2*)&As[kk][ty * 4];
            float4 bv = *(const float4*)&Bs[kk][tx * 4];
            u64 b0 = pack2(bv.x, bv.x), b1 = pack2(bv.y, bv.y);
            u64 b2 = pack2(bv.z, bv.z), b3 = pack2(bv.w, bv.w);
            acc2[0][0] = ffma2(av.x, b0, acc2[0][0]);
            acc2[0][1] = ffma2(av.x, b1, acc2[0][1]);
            acc2[0][2] = ffma2(av.x, b2, acc2[0][2]);
            acc2[0][3] = ffma2(av.x, b3, acc2[0][3]);
            acc2[1][0] = ffma2(av.y, b0, acc2[1][0]);
            acc2[1][1] = ffma2(av.y, b1, acc2[1][1]);
            acc2[1][2] = ffma2(av.y, b2, acc2[1][2]);
            acc2[1][3] = ffma2(av.y, b3, acc2[1][3]);
        }
        __syncthreads();
    }

    #pragma unroll
    for (int ip = 0; ip < 2; ip++) {
        #pragma unroll
        for (int j = 0; j < 4; j++) {
            float2 v = unpack2(acc2[ip][j]);
            int n = n0 + tx * 4 + j;
            float bb = bo[n];
            int m = m0 + ty * 4 + ip * 2;
            out[(size_t)m * DM + n] = v.x + bb;
            out[(size_t)(m + 1) * DM + n] = v.y + bb;
        }
    }
}

// ---------------------------------------------------------------------------
// Fused CoPE attention per (h, b, 16 s-rows). 256 threads, ~213KB smem.
// ---------------------------------------------------------------------------
__global__ __launch_bounds__(256) void cope_attn(const float* __restrict__ pe,
                                                 float* __restrict__ ctx)
{
    extern __shared__ float sm[];
    float* s_log = sm + OFF_LOG;
    float* s_li  = sm + OFF_LI;
    float* s_att = sm + OFF_LI;     // reuses li region (+overflow into old pos area)
    float* s_aux = sm + OFF_AUX;
    float* s_qT  = sm + OFF_QT;

    const int tid = threadIdx.x;
    const int bid = blockIdx.x;
    const int hb = bid >> 6;           // 64 s-tiles per (h,b)
    const int s0 = (bid & 63) * TS;
    const int h = hb >> 2, b = hb & 3;

    const float* qb = g_q + (size_t)hb * SEQ * HD;
    const float* kb = g_k + (size_t)hb * SEQ * HD;
    const float* vb = g_v + (size_t)hb * SEQ * HD;

    // Load qT[d][r]  (d-major for broadcast-friendly inner loop)
    for (int l = tid; l < TS * HD; l += 256) {
        int d = l & 63, r = l >> 6;
        s_qT[d * 16 + r] = qb[(size_t)(s0 + r) * HD + d];
    }
    __syncthreads();

    const int tr = tid >> 7;       // 0..1 : rows tr*8 .. tr*8+7
    const int tc = tid & 127;      // cols tc*2, tc*2+1
    const float scale = 0.125f;    // 1/sqrt(64)

    // ---------------- Phase A: logits = scale * q k^T ----------------
    for (int t0 = 0; t0 < SEQ; t0 += CHUNK) {
        for (int l = tid; l < CHUNK * 16; l += 256) {
            int c = l >> 4, dg = (l & 15) << 2;
            float4 kv = *(const float4*)(kb + (size_t)(t0 + c) * HD + dg);
            float* dst = s_aux + dg * KTP + c;
            dst[0] = kv.x; dst[KTP] = kv.y; dst[2 * KTP] = kv.z; dst[3 * KTP] = kv.w;
        }
        __syncthreads();

        u64 acc[4][2] = {};
        #pragma unroll 8
        for (int d = 0; d < HD; d++) {
            ulonglong2 a01 = *(const ulonglong2*)(s_qT + d * 16 + tr * 8);
            ulonglong2 a23 = *(const ulonglong2*)(s_qT + d * 16 + tr * 8 + 4);
            float2 bv = *(const float2*)(s_aux + d * KTP + tc * 2);
            u64 b0 = pack2(bv.x, bv.x), b1 = pack2(bv.y, bv.y);
            acc[0][0] = ffma2(a01.x, b0, acc[0][0]);
            acc[0][1] = ffma2(a01.x, b1, acc[0][1]);
            acc[1][0] = ffma2(a01.y, b0, acc[1][0]);
            acc[1][1] = ffma2(a01.y, b1, acc[1][1]);
            acc[2][0] = ffma2(a23.x, b0, acc[2][0]);
            acc[2][1] = ffma2(a23.x, b1, acc[2][1]);
            acc[3][0] = ffma2(a23.y, b0, acc[3][0]);
            acc[3][1] = ffma2(a23.y, b1, acc[3][1]);
        }
        #pragma unroll
        for (int rp = 0; rp < 4; rp++) {
            #pragma unroll
            for (int j = 0; j < 2; j++) {
                float2 v = unpack2(acc[rp][j]);
                int row = tr * 8 + rp * 2;
                int col = t0 + tc * 2 + j;
                s_log[row * 1024 + col] = v.x * scale;
                s_log[(row + 1) * 1024 + col] = v.y * scale;
            }
        }
        __syncthreads();
    }

    // ---------------- Phase C: li[r][n] = q · pos_emb[:,n] ----------------
    for (int n0 = 0; n0 < 1024; n0 += CHUNK) {
        for (int l = tid; l < 64 * 64; l += 256) {
            int d = l >> 6, cq = (l & 63) << 2;
            int base = n0 + cq;
            float4 pv = make_float4(0.f, 0.f, 0.f, 0.f);
            if (base + 3 < NPOS) {
                pv = *(const float4*)(pe + (size_t)d * NPOS + base);
            } else {
                if (base + 0 < NPOS) pv.x = pe[(size_t)d * NPOS + base + 0];
                if (base + 1 < NPOS) pv.y = pe[(size_t)d * NPOS + base + 1];
                if (base + 2 < NPOS) pv.z = pe[(size_t)d * NPOS + base + 2];
                if (base + 3 < NPOS) pv.w = pe[(size_t)d * NPOS + base + 3];
            }
            *(float4*)(s_aux + d * PEP + cq) = pv;
        }
        __syncthreads();

        u64 acc[4][2] = {};
        #pragma unroll 8
        for (int d = 0; d < HD; d++) {
            ulonglong2 a01 = *(const ulonglong2*)(s_qT + d * 16 + tr * 8);
            ulonglong2 a23 = *(const ulonglong2*)(s_qT + d * 16 + tr * 8 + 4);
            float2 bv = *(const float2*)(s_aux + d * PEP + tc * 2);
            u64 b0 = pack2(bv.x, bv.x), b1 = pack2(bv.y, bv.y);
            acc[0][0] = ffma2(a01.x, b0, acc[0][0]);
            acc[0][1] = ffma2(a01.x, b1, acc[0][1]);
            acc[1][0] = ffma2(a01.y, b0, acc[1][0]);
            acc[1][1] = ffma2(a01.y, b1, acc[1][1]);
            acc[2][0] = ffma2(a23.x, b0, acc[2][0]);
            acc[2][1] = ffma2(a23.x, b1, acc[2][1]);
            acc[3][0] = ffma2(a23.y, b0, acc[3][0]);
            acc[3][1] = ffma2(a23.y, b1, acc[3][1]);
        }
        #pragma unroll
        for (int rp = 0; rp < 4; rp++) {
            #pragma unroll
            for (int j = 0; j < 2; j++) {
                float2 v = unpack2(acc[rp][j]);
                int row = tr * 8 + rp * 2;
                int col = n0 + tc * 2 + j;
                s_li[row * 1024 + col] = v.x;
                s_li[(row + 1) * 1024 + col] = v.y;
            }
        }
        __syncthreads();
    }

    // ---------------- Phase B: pos = clamp(rev-cumsum(sigmoid(logits))) ----
    {
        int lane = tid & 31, warp = tid >> 5;
        for (int rr = 0; rr < 2; rr++) {
            int r = warp + rr * 8;
            const float* L = s_log + r * 1024;
            float* P = s_aux + r * 1024;
            float carry = 0.f;
            for (int seg = 7; seg >= 0; seg--) {
                float4 lv = *(const float4*)(L + seg * 128 + lane * 4);
                float g0 = sigmoidf_(lv.x), g1 = sigmoidf_(lv.y);
                float g2 = sigmoidf_(lv.z), g3 = sigmoidf_(lv.w);
                float su3 = g3;
                float su2 = g2 + su3;
                float su1 = g1 + su2;
                float su0 = g0 + su1;
                float v = su0;
                #pragma unroll
                for (int off = 1; off < 32; off <<= 1) {
                    float n = __shfl_down_sync(0xffffffffu, v, off);
                    if (lane + off < 32) v += n;
                }
                float tot = __shfl_sync(0xffffffffu, v, 0);
                float base = carry + (v - su0);
                float4 pv;
                pv.x = fminf(base + su0, 999.f);
                pv.y = fminf(base + su1, 999.f);
                pv.z = fminf(base + su2, 999.f);
                pv.w = fminf(base + su3, 999.f);
                *(float4*)(P + seg * 128 + lane * 4) = pv;
                carry += tot;
            }
        }
    }
    __syncthreads();

    // ---------------- Phase D: logits += interp(li, pos) ----------------
    for (int idx = tid; idx < TS * 1024; idx += 256) {
        int r = idx >> 10;
        float p = s_aux[idx];
        float pf = floorf(p);
        float w = p - pf;
        int fi = (int)pf;
        int ci = (int)ceilf(p);
        const float* lir = s_li + (r << 10);
        s_log[idx] += lir[ci] * w + lir[fi] * (1.0f - w);
    }
    __syncthreads();

    // ---------------- Phase E: softmax, write transposed attnT[k][r] ------
    {
        int lane = tid & 31, warp = tid >> 5;
        for (int rr = 0; rr < 2; rr++) {
            int r = warp + rr * 8;
            const float* L = s_log + (r << 10);
            float m = -INFINITY;
            for (int j = lane; j < 1024; j += 32) m = fmaxf(m, L[j]);
            #pragma unroll
            for (int off = 16; off; off >>= 1)
                m = fmaxf(m, __shfl_xor_sync(0xffffffffu, m, off));
            float sum = 0.f;
            for (int j = lane; j < 1024; j += 32) {
                float e = __expf(L[j] - m);
                s_att[j * ATP + r] = e;
                sum += e;
            }
            #pragma unroll
            for (int off = 16; off; off >>= 1)
                sum += __shfl_xor_sync(0xffffffffu, sum, off);
            float inv = 1.0f / sum;
            for (int j = lane; j < 1024; j += 32)
                s_att[j * ATP + r] *= inv;
        }
    }
    __syncthreads();

    // ---------------- Phase F: out = attn · v  (split-K over 4 groups) ----
    {
        const int g = tid >> 6;            // 0..3 : k sub-range
        const int tu = (tid >> 4) & 3;     // row group: rows tu*4..tu*4+3
        const int tcf = tid & 15;          // col group: cols tcf*4..tcf*4+3

        u64 acc[2][4] = {};
        for (int kc = 0; kc < 8; kc++) {
            for (int l = tid; l < 128 * 16; l += 256) {
                int k = l >> 4, dg = (l & 15) << 2;
                float4 vv = *(const float4*)(vb + (size_t)(kc * 128 + k) * HD + dg);
                *(float4*)(s_aux + k * VTP + dg) = vv;
            }
            __syncthreads();

            const float* attp = s_att + (size_t)(kc * 128 + g * 32) * ATP + tu * 4;
            const float* vtp  = s_aux + (g * 32) * VTP + tcf * 4;
            #pragma unroll 4
            for (int kk = 0; kk < 32; kk++) {
                ulonglong2 a2v = *(const ulonglong2*)(attp + kk * ATP);
                float4 vv = *(const float4*)(vtp + kk * VTP);
                u64 v0 = pack2(vv.x, vv.x), v1 = pack2(vv.y, vv.y);
                u64 v2 = pack2(vv.z, vv.z), v3 = pack2(vv.w, vv.w);
                acc[0][0] = ffma2(a2v.x, v0, acc[0][0]);
                acc[0][1] = ffma2(a2v.x, v1, acc[0][1]);
                acc[0][2] = ffma2(a2v.x, v2, acc[0][2]);
                acc[0][3] = ffma2(a2v.x, v3, acc[0][3]);
                acc[1][0] = ffma2(a2v.y, v0, acc[1][0]);
                acc[1][1] = ffma2(a2v.y, v1, acc[1][1]);
                acc[1][2] = ffma2(a2v.y, v2, acc[1][2]);
                acc[1][3] = ffma2(a2v.y, v3, acc[1][3]);
            }
            __syncthreads();
        }

        // stage partials: red[g][row*64+col]
        float* red = s_aux;
        #pragma unroll
        for (int rp = 0; rp < 2; rp++) {
            #pragma unroll
            for (int j = 0; j < 4; j++) {
                float2 v = unpack2(acc[rp][j]);
                int row0 = tu * 4 + rp * 2;
                red[g * 1024 + row0 * 64 + tcf * 4 + j] = v.x;
                red[g * 1024 + (row0 + 1) * 64 + tcf * 4 + j] = v.y;
            }
        }
        __syncthreads();

        // final reduce + write to ctx
        {
            int o = tid * 4;
            float4 r0 = *(const float4*)(red + o);
            float4 r1 = *(const float4*)(red + 1024 + o);
            float4 r2 = *(const float4*)(red + 2048 + o);
            float4 r3 = *(const float4*)(red + 3072 + o);
            float4 s;
            s.x = (r0.x + r1.x) + (r2.x + r3.x);
            s.y = (r0.y + r1.y) + (r2.y + r3.y);
            s.z = (r0.z + r1.z) + (r2.z + r3.z);
            s.w = (r0.w + r1.w) + (r2.w + r3.w);
            int row = o >> 6, d = o & 63;
            *(float4*)(ctx + ((size_t)(s0 + row) * BATCH + b) * DM + h * HD + d) = s;
        }
    }
}

// ---------------------------------------------------------------------------
extern "C" void kernel_launch(void* const* d_in, const int* in_sizes, int n_in,
                              void* d_out, int out_size)
{
    const float* x  = (const float*)d_in[0];
    const float* Wq = (const float*)d_in[1];
    const float* bq = (const float*)d_in[2];
    const float* Wk = (const float*)d_in[3];
    const float* bk = (const float*)d_in[4];
    const float* Wv = (const float*)d_in[5];
    const float* bv = (const float*)d_in[6];
    const float* Wo = (const float*)d_in[7];
    const float* bo = (const float*)d_in[8];
    const float* pe = (const float*)d_in[9];
    float* out = (float*)d_out;

    const int smem_bytes = SM_FLOATS * sizeof(float);  // 218112
    cudaFuncSetAttribute(cope_attn, cudaFuncAttributeMaxDynamicSharedMemorySize,
                         smem_bytes);

    float* ctx;
    cudaGetSymbolAddress((void**)&ctx, g_ctx);

    dim3 gqkv(DM / 64, NTOK / 64, 3);
    qkv_gemm<<<gqkv, 256>>>(x, Wq, bq, Wk, bk, Wv, bv);

    cope_attn<<<NH * BATCH * (SEQ / TS), 256, smem_bytes>>>(pe, ctx);

    dim3 gout(DM / 64, NTOK / 64);
    out_gemm<<<gout, 256>>>(Wo, bo, out);
}

// round 3
// speedup vs baseline: 2.3697x; 1.8457x over previous
#include <cuda_runtime.h>
#include <math.h>

#define SEQ   1024
#define BATCH 4
#define DM    1024
#define NH    16
#define HD    64
#define NPOS  1000
#define NTOK  (SEQ*BATCH)   // 4096
#define NHB   (NH*BATCH)    // 64

typedef unsigned long long u64;

__device__ __forceinline__ u64 ffma2(u64 a, u64 b, u64 c) {
    u64 d;
    asm("fma.rn.f32x2 %0, %1, %2, %3;" : "=l"(d) : "l"(a), "l"(b), "l"(c));
    return d;
}
__device__ __forceinline__ u64 add2(u64 a, u64 b) {
    u64 d;
    asm("add.rn.f32x2 %0, %1, %2;" : "=l"(d) : "l"(a), "l"(b));
    return d;
}
__device__ __forceinline__ u64 mul2(u64 a, u64 b) {
    u64 d;
    asm("mul.rn.f32x2 %0, %1, %2;" : "=l"(d) : "l"(a), "l"(b));
    return d;
}
__device__ __forceinline__ u64 pack2(float x, float y) {
    u64 d;
    asm("mov.b64 %0, {%1, %2};" : "=l"(d) : "f"(x), "f"(y));
    return d;
}
__device__ __forceinline__ float sigmoidf_(float x) {
    return 1.0f / (1.0f + __expf(-x));
}

// Scratch (device globals; no runtime allocation allowed)
__device__ float g_q[NHB*SEQ*HD];
__device__ float g_k[NHB*SEQ*HD];
__device__ float g_v[NHB*SEQ*HD];
__device__ float g_ctx[NTOK*DM];
__device__ float g_logits[(size_t)NHB*SEQ*SEQ];   // 268 MB; becomes attn probs
__device__ float g_li[(size_t)NHB*SEQ*SEQ];       // 268 MB; q·pos_emb (1024-padded)

// ---------------------------------------------------------------------------
// 8x8 micro step: A scalar-broadcast side (As[m][k], pitch AP),
// B paired side (Bs[k][n], pitch BP). acc[i][j] = c[m0+i][n0+2j, 2j+1].
// ---------------------------------------------------------------------------
template<int AP, int BP>
__device__ __forceinline__ void micro8x8(const float* __restrict__ As,
                                         const float* __restrict__ Bs,
                                         int m0, int n0, int kk, u64 acc[8][4])
{
    const float* ap = As + m0 * AP + kk;
    ulonglong2 b01 = *(const ulonglong2*)(Bs + kk * BP + n0);
    ulonglong2 b23 = *(const ulonglong2*)(Bs + kk * BP + n0 + 4);
    u64 b0 = b01.x, b1 = b01.y, b2 = b23.x, b3 = b23.y;
    #pragma unroll
    for (int i = 0; i < 8; i++) {
        float av = ap[i * AP];
        u64 ad = pack2(av, av);
        acc[i][0] = ffma2(b0, ad, acc[i][0]);
        acc[i][1] = ffma2(b1, ad, acc[i][1]);
        acc[i][2] = ffma2(b2, ad, acc[i][2]);
        acc[i][3] = ffma2(b3, ad, acc[i][3]);
    }
}

// ---------------------------------------------------------------------------
// K1: QKV projections. 128x128 tile, kt=16, 8x8 micro. Scatter to head layout.
// ---------------------------------------------------------------------------
__global__ __launch_bounds__(256, 2) void qkv_gemm(
    const float* __restrict__ x,
    const float* __restrict__ Wq, const float* __restrict__ bq,
    const float* __restrict__ Wk, const float* __restrict__ bk,
    const float* __restrict__ Wv, const float* __restrict__ bv)
{
    const float* W;  const float* bias;  float* out;
    if (blockIdx.z == 0)      { W = Wq; bias = bq; out = g_q; }
    else if (blockIdx.z == 1) { W = Wk; bias = bk; out = g_k; }
    else                      { W = Wv; bias = bv; out = g_v; }

    __shared__ __align__(16) float As[128 * 20];
    __shared__ __align__(16) float Bs[16 * 132];

    const int tid = threadIdx.x;
    const int m0b = blockIdx.y * 128;
    const int n0b = blockIdx.x * 128;
    const int tx = tid & 15, ty = tid >> 4;

    u64 acc[8][4] = {};

    for (int k0 = 0; k0 < DM; k0 += 16) {
        // A tile 128x16 (row-major, pitch 20)
        #pragma unroll
        for (int i2 = 0; i2 < 2; i2++) {
            int q = tid + i2 * 256;
            int m = q >> 2, kq = (q & 3) * 4;
            float4 v = *(const float4*)(x + (size_t)(m0b + m) * DM + k0 + kq);
            *(float4*)(As + m * 20 + kq) = v;
        }
        // B tile 16x128 (row-major, pitch 132)
        #pragma unroll
        for (int i2 = 0; i2 < 2; i2++) {
            int q = tid + i2 * 256;
            int k = q >> 5, nq = (q & 31) * 4;
            float4 v = *(const float4*)(W + (size_t)(k0 + k) * DM + n0b + nq);
            *(float4*)(Bs + k * 132 + nq) = v;
        }
        __syncthreads();
        #pragma unroll
        for (int kk = 0; kk < 16; kk++)
            micro8x8<20, 132>(As, Bs, ty * 8, tx * 8, kk, acc);
        __syncthreads();
    }

    #pragma unroll
    for (int i = 0; i < 8; i++) {
        int m = m0b + ty * 8 + i;
        int s = m >> 2, b_ = m & 3;
        #pragma unroll
        for (int j = 0; j < 4; j++) {
            int n = n0b + tx * 8 + 2 * j;
            int h = n >> 6, d = n & 63;
            u64 bb = *(const u64*)(bias + n);
            u64 r = add2(acc[i][j], bb);
            *(u64*)(out + ((size_t)(h * BATCH + b_) * SEQ + s) * HD + d) = r;
        }
    }
}

// ---------------------------------------------------------------------------
// K2: logits = scale * Q K^T per (h,b). 128x128, single K stage (K=64).
// ---------------------------------------------------------------------------
__global__ __launch_bounds__(256, 2) void qk_gemm()
{
    extern __shared__ __align__(16) float dsm[];
    float* As = dsm;                 // 128 x 68 (Q, [m][k])
    float* Bs = dsm + 128 * 68;      // 64 x 132 (K^T, [k][n])

    const int tid = threadIdx.x;
    const int hb = blockIdx.z;
    const int m0b = blockIdx.y * 128;   // s rows
    const int t0b = blockIdx.x * 128;   // t cols
    const int tx = tid & 15, ty = tid >> 4;

    const float* qb = g_q + (size_t)hb * SEQ * HD;
    const float* kb = g_k + (size_t)hb * SEQ * HD;

    // Q tile: coalesced rows
    #pragma unroll
    for (int it = 0; it < 8; it++) {
        int q = tid + it * 256;
        int m = q >> 4, kq = (q & 15) * 4;
        float4 v = *(const float4*)(qb + (size_t)(m0b + m) * HD + kq);
        *(float4*)(As + m * 68 + kq) = v;
    }
    // K tile: transpose on store (n-consecutive STS, conflict-free)
    #pragma unroll
    for (int it = 0; it < 8; it++) {
        int q = tid + it * 256;
        int n = q & 127, kq = (q >> 7) * 4;
        float4 v = *(const float4*)(kb + (size_t)(t0b + n) * HD + kq);
        Bs[(kq + 0) * 132 + n] = v.x;
        Bs[(kq + 1) * 132 + n] = v.y;
        Bs[(kq + 2) * 132 + n] = v.z;
        Bs[(kq + 3) * 132 + n] = v.w;
    }
    __syncthreads();

    u64 acc[8][4] = {};
    #pragma unroll 8
    for (int kk = 0; kk < HD; kk++)
        micro8x8<68, 132>(As, Bs, ty * 8, tx * 8, kk, acc);

    const u64 sc = pack2(0.125f, 0.125f);
    float* Lb = g_logits + ((size_t)hb << 20);
    #pragma unroll
    for (int i = 0; i < 8; i++) {
        int m = m0b + ty * 8 + i;
        float* row = Lb + (size_t)m * SEQ + t0b + tx * 8;
        ulonglong2 r0, r1;
        r0.x = mul2(acc[i][0], sc); r0.y = mul2(acc[i][1], sc);
        r1.x = mul2(acc[i][2], sc); r1.y = mul2(acc[i][3], sc);
        *(ulonglong2*)(row) = r0;
        *(ulonglong2*)(row + 4) = r1;
    }
}

// ---------------------------------------------------------------------------
// K3: li = Q · pos_emb per (h,b). 128x128 (n padded to 1024), K=64.
// ---------------------------------------------------------------------------
__global__ __launch_bounds__(256, 2) void qpe_gemm(const float* __restrict__ pe)
{
    extern __shared__ __align__(16) float dsm[];
    float* As = dsm;                 // 128 x 68 (Q)
    float* Bs = dsm + 128 * 68;      // 64 x 132 (PE, [d][n])

    const int tid = threadIdx.x;
    const int hb = blockIdx.z;
    const int m0b = blockIdx.y * 128;
    const int n0b = blockIdx.x * 128;
    const int tx = tid & 15, ty = tid >> 4;

    const float* qb = g_q + (size_t)hb * SEQ * HD;

    #pragma unroll
    for (int it = 0; it < 8; it++) {
        int q = tid + it * 256;
        int m = q >> 4, kq = (q & 15) * 4;
        float4 v = *(const float4*)(qb + (size_t)(m0b + m) * HD + kq);
        *(float4*)(As + m * 68 + kq) = v;
    }
    // PE tile: already [k][n]; zero-fill n >= NPOS (row stride 1000 floats,
    // 4000 B, 16B-aligned, so quads never straddle).
    #pragma unroll
    for (int it = 0; it < 8; it++) {
        int q = tid + it * 256;
        int k = q >> 5, nq = (q & 31) * 4;
        int ng = n0b + nq;
        float4 v = make_float4(0.f, 0.f, 0.f, 0.f);
        if (ng + 3 < NPOS)
            v = *(const float4*)(pe + (size_t)k * NPOS + ng);
        else if (ng < NPOS) {
            v.x = pe[(size_t)k * NPOS + ng];
            if (ng + 1 < NPOS) v.y = pe[(size_t)k * NPOS + ng + 1];
            if (ng + 2 < NPOS) v.z = pe[(size_t)k * NPOS + ng + 2];
        }
        *(float4*)(Bs + k * 132 + nq) = v;
    }
    __syncthreads();

    u64 acc[8][4] = {};
    #pragma unroll 8
    for (int kk = 0; kk < HD; kk++)
        micro8x8<68, 132>(As, Bs, ty * 8, tx * 8, kk, acc);

    float* Lb = g_li + ((size_t)hb << 20);
    #pragma unroll
    for (int i = 0; i < 8; i++) {
        int m = m0b + ty * 8 + i;
        float* row = Lb + (size_t)m * SEQ + n0b + tx * 8;
        ulonglong2 r0, r1;
        r0.x = acc[i][0]; r0.y = acc[i][1];
        r1.x = acc[i][2]; r1.y = acc[i][3];
        *(ulonglong2*)(row) = r0;
        *(ulonglong2*)(row + 4) = r1;
    }
}

// ---------------------------------------------------------------------------
// K4: per-row CoPE + softmax, in place on g_logits.
// One block (128 thr) per row; each thread owns 8 consecutive elements.
// ---------------------------------------------------------------------------
__global__ __launch_bounds__(128) void cope_softmax()
{
    __shared__ __align__(16) float s_li[SEQ];
    __shared__ float s_w[4];
    __shared__ float s_m[4];
    __shared__ float s_s[4];

    const size_t row = blockIdx.x;
    float* L = g_logits + (row << 10);
    const float* li = g_li + (row << 10);
    const int tid = threadIdx.x;
    const int lane = tid & 31, warp = tid >> 5;

    // stage li row
    #pragma unroll
    for (int i = 0; i < 2; i++)
        *(float4*)(s_li + tid * 4 + i * 512) = *(const float4*)(li + tid * 4 + i * 512);

    // load logits (8 contiguous elems per thread)
    float l[8];
    {
        float4 a = *(const float4*)(L + tid * 8);
        float4 b = *(const float4*)(L + tid * 8 + 4);
        l[0] = a.x; l[1] = a.y; l[2] = a.z; l[3] = a.w;
        l[4] = b.x; l[5] = b.y; l[6] = b.z; l[7] = b.w;
    }

    // local suffix sums of gates
    float su[8];
    {
        float g = sigmoidf_(l[7]); su[7] = g;
        #pragma unroll
        for (int j = 6; j >= 0; j--) su[j] = su[j + 1] + sigmoidf_(l[j]);
    }
    float total = su[0];

    // warp inclusive suffix scan of totals
    float v = total;
    #pragma unroll
    for (int off = 1; off < 32; off <<= 1) {
        float n = __shfl_down_sync(0xffffffffu, v, off);
        if (lane + off < 32) v += n;
    }
    if (lane == 0) s_w[warp] = v;   // warp grand total
    __syncthreads();                // also covers s_li staging

    float basew = 0.f;
    #pragma unroll
    for (int w = 0; w < 4; w++) if (w > warp) basew += s_w[w];
    float base = basew + (v - total);

    // pos -> interp -> add
    #pragma unroll
    for (int j = 0; j < 8; j++) {
        float p = fminf(base + su[j], 999.0f);
        float pf = floorf(p);
        float w = p - pf;
        int fi = (int)pf;
        int ci = (int)ceilf(p);
        l[j] += s_li[ci] * w + s_li[fi] * (1.0f - w);
    }

    // softmax
    float m = l[0];
    #pragma unroll
    for (int j = 1; j < 8; j++) m = fmaxf(m, l[j]);
    #pragma unroll
    for (int off = 16; off; off >>= 1)
        m = fmaxf(m, __shfl_xor_sync(0xffffffffu, m, off));
    if (lane == 0) s_m[warp] = m;
    __syncthreads();
    m = fmaxf(fmaxf(s_m[0], s_m[1]), fmaxf(s_m[2], s_m[3]));

    float sum = 0.f;
    #pragma unroll
    for (int j = 0; j < 8; j++) { l[j] = __expf(l[j] - m); sum += l[j]; }
    #pragma unroll
    for (int off = 16; off; off >>= 1)
        sum += __shfl_xor_sync(0xffffffffu, sum, off);
    if (lane == 0) s_s[warp] = sum;
    __syncthreads();
    float inv = 1.0f / (s_s[0] + s_s[1] + s_s[2] + s_s[3]);

    float4 o0 = make_float4(l[0] * inv, l[1] * inv, l[2] * inv, l[3] * inv);
    float4 o1 = make_float4(l[4] * inv, l[5] * inv, l[6] * inv, l[7] * inv);
    *(float4*)(L + tid * 8) = o0;
    *(float4*)(L + tid * 8 + 4) = o1;
}

// ---------------------------------------------------------------------------
// K5: ctx = attn · V per (h,b). 256x64 tile, kt=16, 8x8 micro (tx:8, ty:32).
// ---------------------------------------------------------------------------
__global__ __launch_bounds__(256, 2) void av_gemm()
{
    __shared__ __align__(16) float As[256 * 20];
    __shared__ __align__(16) float Bs[16 * 68];

    const int tid = threadIdx.x;
    const int hb = blockIdx.y;
    const int m0b = blockIdx.x * 256;
    const int h = hb >> 2, b_ = hb & 3;
    const int tx = tid & 7, ty = tid >> 3;

    const float* Ab = g_logits + ((size_t)hb << 20);
    const float* Vb = g_v + (size_t)hb * SEQ * HD;

    u64 acc[8][4] = {};

    for (int k0 = 0; k0 < SEQ; k0 += 16) {
        #pragma unroll
        for (int it = 0; it < 4; it++) {
            int q = tid + it * 256;
            int m = q >> 2, kq = (q & 3) * 4;
            float4 v = *(const float4*)(Ab + (size_t)(m0b + m) * SEQ + k0 + kq);
            *(float4*)(As + m * 20 + kq) = v;
        }
        {
            int k = tid >> 4, nq = (tid & 15) * 4;
            float4 v = *(const float4*)(Vb + (size_t)(k0 + k) * HD + nq);
            *(float4*)(Bs + k * 68 + nq) = v;
        }
        __syncthreads();
        #pragma unroll
        for (int kk = 0; kk < 16; kk++)
            micro8x8<20, 68>(As, Bs, ty * 8, tx * 8, kk, acc);
        __syncthreads();
    }

    #pragma unroll
    for (int i = 0; i < 8; i++) {
        int s = m0b + ty * 8 + i;
        float* row = g_ctx + ((size_t)s * BATCH + b_) * DM + h * HD + tx * 8;
        ulonglong2 r0, r1;
        r0.x = acc[i][0]; r0.y = acc[i][1];
        r1.x = acc[i][2]; r1.y = acc[i][3];
        *(ulonglong2*)(row) = r0;
        *(ulonglong2*)(row + 4) = r1;
    }
}

// ---------------------------------------------------------------------------
// K6: output projection. Same structure as K1, direct row-major output + bias.
// ---------------------------------------------------------------------------
__global__ __launch_bounds__(256, 2) void out_gemm(
    const float* __restrict__ Wo, const float* __restrict__ bo,
    float* __restrict__ out)
{
    __shared__ __align__(16) float As[128 * 20];
    __shared__ __align__(16) float Bs[16 * 132];

    const int tid = threadIdx.x;
    const int m0b = blockIdx.y * 128;
    const int n0b = blockIdx.x * 128;
    const int tx = tid & 15, ty = tid >> 4;

    u64 acc[8][4] = {};

    for (int k0 = 0; k0 < DM; k0 += 16) {
        #pragma unroll
        for (int i2 = 0; i2 < 2; i2++) {
            int q = tid + i2 * 256;
            int m = q >> 2, kq = (q & 3) * 4;
            float4 v = *(const float4*)(g_ctx + (size_t)(m0b + m) * DM + k0 + kq);
            *(float4*)(As + m * 20 + kq) = v;
        }
        #pragma unroll
        for (int i2 = 0; i2 < 2; i2++) {
            int q = tid + i2 * 256;
            int k = q >> 5, nq = (q & 31) * 4;
            float4 v = *(const float4*)(Wo + (size_t)(k0 + k) * DM + n0b + nq);
            *(float4*)(Bs + k * 132 + nq) = v;
        }
        __syncthreads();
        #pragma unroll
        for (int kk = 0; kk < 16; kk++)
            micro8x8<20, 132>(As, Bs, ty * 8, tx * 8, kk, acc);
        __syncthreads();
    }

    #pragma unroll
    for (int i = 0; i < 8; i++) {
        int m = m0b + ty * 8 + i;
        float* row = out + (size_t)m * DM + n0b + tx * 8;
        #pragma unroll
        for (int j = 0; j < 4; j++) {
            u64 bb = *(const u64*)(bo + n0b + tx * 8 + 2 * j);
            *(u64*)(row + 2 * j) = add2(acc[i][j], bb);
        }
    }
}

// ---------------------------------------------------------------------------
extern "C" void kernel_launch(void* const* d_in, const int* in_sizes, int n_in,
                              void* d_out, int out_size)
{
    const float* x  = (const float*)d_in[0];
    const float* Wq = (const float*)d_in[1];
    const float* bq = (const float*)d_in[2];
    const float* Wk = (const float*)d_in[3];
    const float* bk = (const float*)d_in[4];
    const float* Wv = (const float*)d_in[5];
    const float* bv = (const float*)d_in[6];
    const float* Wo = (const float*)d_in[7];
    const float* bo = (const float*)d_in[8];
    const float* pe = (const float*)d_in[9];
    float* out = (float*)d_out;

    const int dsm_bytes = (128 * 68 + 64 * 132) * sizeof(float);  // 68608
    static int configured = 0;
    if (!configured) {
        cudaFuncSetAttribute(qk_gemm,  cudaFuncAttributeMaxDynamicSharedMemorySize, dsm_bytes);
        cudaFuncSetAttribute(qpe_gemm, cudaFuncAttributeMaxDynamicSharedMemorySize, dsm_bytes);
        configured = 1;
    }

    dim3 gqkv(DM / 128, NTOK / 128, 3);
    qkv_gemm<<<gqkv, 256>>>(x, Wq, bq, Wk, bk, Wv, bv);

    dim3 gqk(SEQ / 128, SEQ / 128, NHB);
    qk_gemm<<<gqk, 256, dsm_bytes>>>();
    qpe_gemm<<<gqk, 256, dsm_bytes>>>(pe);

    cope_softmax<<<NHB * SEQ, 128>>>();

    dim3 gav(SEQ / 256, NHB);
    av_gemm<<<gav, 256>>>();

    dim3 gout(DM / 128, NTOK / 128);
    out_gemm<<<gout, 256>>>(Wo, bo, out);
}

// round 4
// speedup vs baseline: 2.3704x; 1.0003x over previous
#include <cuda_runtime.h>
#include <math.h>

#define SEQ   1024
#define BATCH 4
#define DM    1024
#define NH    16
#define HD    64
#define NPOS  1000
#define NTOK  (SEQ*BATCH)   // 4096
#define NHB   (NH*BATCH)    // 64

typedef unsigned long long u64;

__device__ __forceinline__ u64 ffma2(u64 a, u64 b, u64 c) {
    u64 d;
    asm("fma.rn.f32x2 %0, %1, %2, %3;" : "=l"(d) : "l"(a), "l"(b), "l"(c));
    return d;
}
__device__ __forceinline__ u64 add2(u64 a, u64 b) {
    u64 d;
    asm("add.rn.f32x2 %0, %1, %2;" : "=l"(d) : "l"(a), "l"(b));
    return d;
}
__device__ __forceinline__ u64 mul2(u64 a, u64 b) {
    u64 d;
    asm("mul.rn.f32x2 %0, %1, %2;" : "=l"(d) : "l"(a), "l"(b));
    return d;
}
__device__ __forceinline__ u64 pack2(float x, float y) {
    u64 d;
    asm("mov.b64 %0, {%1, %2};" : "=l"(d) : "f"(x), "f"(y));
    return d;
}
__device__ __forceinline__ float sigmoidf_(float x) {
    return 1.0f / (1.0f + __expf(-x));
}

// Scratch (device globals; no runtime allocation allowed)
__device__ float g_q[NHB*SEQ*HD];
__device__ float g_k[NHB*SEQ*HD];
__device__ float g_v[NHB*SEQ*HD];
__device__ float g_ctx[NTOK*DM];
__device__ float g_logits[(size_t)NHB*SEQ*SEQ];   // 268 MB; becomes attn probs
__device__ float g_li[(size_t)NHB*SEQ*SEQ];       // 268 MB; q·pos_emb (1024-padded)

// ---------------------------------------------------------------------------
// 8x8 micro step: A scalar-broadcast side (As[m][k], pitch AP),
// B paired side (Bs[k][n], pitch BP). acc[i][j] = c[m0+i][n0+2j, 2j+1].
// ---------------------------------------------------------------------------
template<int AP, int BP>
__device__ __forceinline__ void micro8x8(const float* __restrict__ As,
                                         const float* __restrict__ Bs,
                                         int m0, int n0, int kk, u64 acc[8][4])
{
    const float* ap = As + m0 * AP + kk;
    ulonglong2 b01 = *(const ulonglong2*)(Bs + kk * BP + n0);
    ulonglong2 b23 = *(const ulonglong2*)(Bs + kk * BP + n0 + 4);
    u64 b0 = b01.x, b1 = b01.y, b2 = b23.x, b3 = b23.y;
    #pragma unroll
    for (int i = 0; i < 8; i++) {
        float av = ap[i * AP];
        u64 ad = pack2(av, av);
        acc[i][0] = ffma2(b0, ad, acc[i][0]);
        acc[i][1] = ffma2(b1, ad, acc[i][1]);
        acc[i][2] = ffma2(b2, ad, acc[i][2]);
        acc[i][3] = ffma2(b3, ad, acc[i][3]);
    }
}

// ---------------------------------------------------------------------------
// K1: QKV projections. 128x128 tile, kt=16, 8x8 micro. Scatter to head layout.
// ---------------------------------------------------------------------------
__global__ __launch_bounds__(256, 2) void qkv_gemm(
    const float* __restrict__ x,
    const float* __restrict__ Wq, const float* __restrict__ bq,
    const float* __restrict__ Wk, const float* __restrict__ bk,
    const float* __restrict__ Wv, const float* __restrict__ bv)
{
    const float* W;  const float* bias;  float* out;
    if (blockIdx.z == 0)      { W = Wq; bias = bq; out = g_q; }
    else if (blockIdx.z == 1) { W = Wk; bias = bk; out = g_k; }
    else                      { W = Wv; bias = bv; out = g_v; }

    __shared__ __align__(16) float As[128 * 20];
    __shared__ __align__(16) float Bs[16 * 132];

    const int tid = threadIdx.x;
    const int m0b = blockIdx.y * 128;
    const int n0b = blockIdx.x * 128;
    const int tx = tid & 15, ty = tid >> 4;

    u64 acc[8][4] = {};

    for (int k0 = 0; k0 < DM; k0 += 16) {
        // A tile 128x16 (row-major, pitch 20)
        #pragma unroll
        for (int i2 = 0; i2 < 2; i2++) {
            int q = tid + i2 * 256;
            int m = q >> 2, kq = (q & 3) * 4;
            float4 v = *(const float4*)(x + (size_t)(m0b + m) * DM + k0 + kq);
            *(float4*)(As + m * 20 + kq) = v;
        }
        // B tile 16x128 (row-major, pitch 132)
        #pragma unroll
        for (int i2 = 0; i2 < 2; i2++) {
            int q = tid + i2 * 256;
            int k = q >> 5, nq = (q & 31) * 4;
            float4 v = *(const float4*)(W + (size_t)(k0 + k) * DM + n0b + nq);
            *(float4*)(Bs + k * 132 + nq) = v;
        }
        __syncthreads();
        #pragma unroll
        for (int kk = 0; kk < 16; kk++)
            micro8x8<20, 132>(As, Bs, ty * 8, tx * 8, kk, acc);
        __syncthreads();
    }

    #pragma unroll
    for (int i = 0; i < 8; i++) {
        int m = m0b + ty * 8 + i;
        int s = m >> 2, b_ = m & 3;
        #pragma unroll
        for (int j = 0; j < 4; j++) {
            int n = n0b + tx * 8 + 2 * j;
            int h = n >> 6, d = n & 63;
            u64 bb = *(const u64*)(bias + n);
            u64 r = add2(acc[i][j], bb);
            *(u64*)(out + ((size_t)(h * BATCH + b_) * SEQ + s) * HD + d) = r;
        }
    }
}

// ---------------------------------------------------------------------------
// K2: logits = scale * Q K^T per (h,b). 128x128, single K stage (K=64).
// ---------------------------------------------------------------------------
__global__ __launch_bounds__(256, 2) void qk_gemm()
{
    extern __shared__ __align__(16) float dsm[];
    float* As = dsm;                 // 128 x 68 (Q, [m][k])
    float* Bs = dsm + 128 * 68;      // 64 x 132 (K^T, [k][n])

    const int tid = threadIdx.x;
    const int hb = blockIdx.z;
    const int m0b = blockIdx.y * 128;   // s rows
    const int t0b = blockIdx.x * 128;   // t cols
    const int tx = tid & 15, ty = tid >> 4;

    const float* qb = g_q + (size_t)hb * SEQ * HD;
    const float* kb = g_k + (size_t)hb * SEQ * HD;

    // Q tile: coalesced rows
    #pragma unroll
    for (int it = 0; it < 8; it++) {
        int q = tid + it * 256;
        int m = q >> 4, kq = (q & 15) * 4;
        float4 v = *(const float4*)(qb + (size_t)(m0b + m) * HD + kq);
        *(float4*)(As + m * 68 + kq) = v;
    }
    // K tile: transpose on store (n-consecutive STS, conflict-free)
    #pragma unroll
    for (int it = 0; it < 8; it++) {
        int q = tid + it * 256;
        int n = q & 127, kq = (q >> 7) * 4;
        float4 v = *(const float4*)(kb + (size_t)(t0b + n) * HD + kq);
        Bs[(kq + 0) * 132 + n] = v.x;
        Bs[(kq + 1) * 132 + n] = v.y;
        Bs[(kq + 2) * 132 + n] = v.z;
        Bs[(kq + 3) * 132 + n] = v.w;
    }
    __syncthreads();

    u64 acc[8][4] = {};
    #pragma unroll 8
    for (int kk = 0; kk < HD; kk++)
        micro8x8<68, 132>(As, Bs, ty * 8, tx * 8, kk, acc);

    const u64 sc = pack2(0.125f, 0.125f);
    float* Lb = g_logits + ((size_t)hb << 20);
    #pragma unroll
    for (int i = 0; i < 8; i++) {
        int m = m0b + ty * 8 + i;
        float* row = Lb + (size_t)m * SEQ + t0b + tx * 8;
        ulonglong2 r0, r1;
        r0.x = mul2(acc[i][0], sc); r0.y = mul2(acc[i][1], sc);
        r1.x = mul2(acc[i][2], sc); r1.y = mul2(acc[i][3], sc);
        *(ulonglong2*)(row) = r0;
        *(ulonglong2*)(row + 4) = r1;
    }
}

// ---------------------------------------------------------------------------
// K3: li = Q · pos_emb per (h,b). 128x128 (n padded to 1024), K=64.
// ---------------------------------------------------------------------------
__global__ __launch_bounds__(256, 2) void qpe_gemm(const float* __restrict__ pe)
{
    extern __shared__ __align__(16) float dsm[];
    float* As = dsm;                 // 128 x 68 (Q)
    float* Bs = dsm + 128 * 68;      // 64 x 132 (PE, [d][n])

    const int tid = threadIdx.x;
    const int hb = blockIdx.z;
    const int m0b = blockIdx.y * 128;
    const int n0b = blockIdx.x * 128;
    const int tx = tid & 15, ty = tid >> 4;

    const float* qb = g_q + (size_t)hb * SEQ * HD;

    #pragma unroll
    for (int it = 0; it < 8; it++) {
        int q = tid + it * 256;
        int m = q >> 4, kq = (q & 15) * 4;
        float4 v = *(const float4*)(qb + (size_t)(m0b + m) * HD + kq);
        *(float4*)(As + m * 68 + kq) = v;
    }
    // PE tile: already [k][n]; zero-fill n >= NPOS (row stride 1000 floats,
    // 4000 B, 16B-aligned, so quads never straddle).
    #pragma unroll
    for (int it = 0; it < 8; it++) {
        int q = tid + it * 256;
        int k = q >> 5, nq = (q & 31) * 4;
        int ng = n0b + nq;
        float4 v = make_float4(0.f, 0.f, 0.f, 0.f);
        if (ng + 3 < NPOS)
            v = *(const float4*)(pe + (size_t)k * NPOS + ng);
        else if (ng < NPOS) {
            v.x = pe[(size_t)k * NPOS + ng];
            if (ng + 1 < NPOS) v.y = pe[(size_t)k * NPOS + ng + 1];
            if (ng + 2 < NPOS) v.z = pe[(size_t)k * NPOS + ng + 2];
        }
        *(float4*)(Bs + k * 132 + nq) = v;
    }
    __syncthreads();

    u64 acc[8][4] = {};
    #pragma unroll 8
    for (int kk = 0; kk < HD; kk++)
        micro8x8<68, 132>(As, Bs, ty * 8, tx * 8, kk, acc);

    float* Lb = g_li + ((size_t)hb << 20);
    #pragma unroll
    for (int i = 0; i < 8; i++) {
        int m = m0b + ty * 8 + i;
        float* row = Lb + (size_t)m * SEQ + n0b + tx * 8;
        ulonglong2 r0, r1;
        r0.x = acc[i][0]; r0.y = acc[i][1];
        r1.x = acc[i][2]; r1.y = acc[i][3];
        *(ulonglong2*)(row) = r0;
        *(ulonglong2*)(row + 4) = r1;
    }
}

// ---------------------------------------------------------------------------
// K4: per-row CoPE + softmax, in place on g_logits.
// One block (128 thr) per row; each thread owns 8 consecutive elements.
// ---------------------------------------------------------------------------
__global__ __launch_bounds__(128) void cope_softmax()
{
    __shared__ __align__(16) float s_li[SEQ];
    __shared__ float s_w[4];
    __shared__ float s_m[4];
    __shared__ float s_s[4];

    const size_t row = blockIdx.x;
    float* L = g_logits + (row << 10);
    const float* li = g_li + (row << 10);
    const int tid = threadIdx.x;
    const int lane = tid & 31, warp = tid >> 5;

    // stage li row
    #pragma unroll
    for (int i = 0; i < 2; i++)
        *(float4*)(s_li + tid * 4 + i * 512) = *(const float4*)(li + tid * 4 + i * 512);

    // load logits (8 contiguous elems per thread)
    float l[8];
    {
        float4 a = *(const float4*)(L + tid * 8);
        float4 b = *(const float4*)(L + tid * 8 + 4);
        l[0] = a.x; l[1] = a.y; l[2] = a.z; l[3] = a.w;
        l[4] = b.x; l[5] = b.y; l[6] = b.z; l[7] = b.w;
    }

    // local suffix sums of gates
    float su[8];
    {
        float g = sigmoidf_(l[7]); su[7] = g;
        #pragma unroll
        for (int j = 6; j >= 0; j--) su[j] = su[j + 1] + sigmoidf_(l[j]);
    }
    float total = su[0];

    // warp inclusive suffix scan of totals
    float v = total;
    #pragma unroll
    for (int off = 1; off < 32; off <<= 1) {
        float n = __shfl_down_sync(0xffffffffu, v, off);
        if (lane + off < 32) v += n;
    }
    if (lane == 0) s_w[warp] = v;   // warp grand total
    __syncthreads();                // also covers s_li staging

    float basew = 0.f;
    #pragma unroll
    for (int w = 0; w < 4; w++) if (w > warp) basew += s_w[w];
    float base = basew + (v - total);

    // pos -> interp -> add
    #pragma unroll
    for (int j = 0; j < 8; j++) {
        float p = fminf(base + su[j], 999.0f);
        float pf = floorf(p);
        float w = p - pf;
        int fi = (int)pf;
        int ci = (int)ceilf(p);
        l[j] += s_li[ci] * w + s_li[fi] * (1.0f - w);
    }

    // softmax
    float m = l[0];
    #pragma unroll
    for (int j = 1; j < 8; j++) m = fmaxf(m, l[j]);
    #pragma unroll
    for (int off = 16; off; off >>= 1)
        m = fmaxf(m, __shfl_xor_sync(0xffffffffu, m, off));
    if (lane == 0) s_m[warp] = m;
    __syncthreads();
    m = fmaxf(fmaxf(s_m[0], s_m[1]), fmaxf(s_m[2], s_m[3]));

    float sum = 0.f;
    #pragma unroll
    for (int j = 0; j < 8; j++) { l[j] = __expf(l[j] - m); sum += l[j]; }
    #pragma unroll
    for (int off = 16; off; off >>= 1)
        sum += __shfl_xor_sync(0xffffffffu, sum, off);
    if (lane == 0) s_s[warp] = sum;
    __syncthreads();
    float inv = 1.0f / (s_s[0] + s_s[1] + s_s[2] + s_s[3]);

    float4 o0 = make_float4(l[0] * inv, l[1] * inv, l[2] * inv, l[3] * inv);
    float4 o1 = make_float4(l[4] * inv, l[5] * inv, l[6] * inv, l[7] * inv);
    *(float4*)(L + tid * 8) = o0;
    *(float4*)(L + tid * 8 + 4) = o1;
}

// ---------------------------------------------------------------------------
// K5: ctx = attn · V per (h,b). 256x64 tile, kt=16, 8x8 micro (tx:8, ty:32).
// ---------------------------------------------------------------------------
__global__ __launch_bounds__(256, 2) void av_gemm()
{
    __shared__ __align__(16) float As[256 * 20];
    __shared__ __align__(16) float Bs[16 * 68];

    const int tid = threadIdx.x;
    const int hb = blockIdx.y;
    const int m0b = blockIdx.x * 256;
    const int h = hb >> 2, b_ = hb & 3;
    const int tx = tid & 7, ty = tid >> 3;

    const float* Ab = g_logits + ((size_t)hb << 20);
    const float* Vb = g_v + (size_t)hb * SEQ * HD;

    u64 acc[8][4] = {};

    for (int k0 = 0; k0 < SEQ; k0 += 16) {
        #pragma unroll
        for (int it = 0; it < 4; it++) {
            int q = tid + it * 256;
            int m = q >> 2, kq = (q & 3) * 4;
            float4 v = *(const float4*)(Ab + (size_t)(m0b + m) * SEQ + k0 + kq);
            *(float4*)(As + m * 20 + kq) = v;
        }
        {
            int k = tid >> 4, nq = (tid & 15) * 4;
            float4 v = *(const float4*)(Vb + (size_t)(k0 + k) * HD + nq);
            *(float4*)(Bs + k * 68 + nq) = v;
        }
        __syncthreads();
        #pragma unroll
        for (int kk = 0; kk < 16; kk++)
            micro8x8<20, 68>(As, Bs, ty * 8, tx * 8, kk, acc);
        __syncthreads();
    }

    #pragma unroll
    for (int i = 0; i < 8; i++) {
        int s = m0b + ty * 8 + i;
        float* row = g_ctx + ((size_t)s * BATCH + b_) * DM + h * HD + tx * 8;
        ulonglong2 r0, r1;
        r0.x = acc[i][0]; r0.y = acc[i][1];
        r1.x = acc[i][2]; r1.y = acc[i][3];
        *(ulonglong2*)(row) = r0;
        *(ulonglong2*)(row + 4) = r1;
    }
}

// ---------------------------------------------------------------------------
// K6: output projection. Same structure as K1, direct row-major output + bias.
// ---------------------------------------------------------------------------
__global__ __launch_bounds__(256, 2) void out_gemm(
    const float* __restrict__ Wo, const float* __restrict__ bo,
    float* __restrict__ out)
{
    __shared__ __align__(16) float As[128 * 20];
    __shared__ __align__(16) float Bs[16 * 132];

    const int tid = threadIdx.x;
    const int m0b = blockIdx.y * 128;
    const int n0b = blockIdx.x * 128;
    const int tx = tid & 15, ty = tid >> 4;

    u64 acc[8][4] = {};

    for (int k0 = 0; k0 < DM; k0 += 16) {
        #pragma unroll
        for (int i2 = 0; i2 < 2; i2++) {
            int q = tid + i2 * 256;
            int m = q >> 2, kq = (q & 3) * 4;
            float4 v = *(const float4*)(g_ctx + (size_t)(m0b + m) * DM + k0 + kq);
            *(float4*)(As + m * 20 + kq) = v;
        }
        #pragma unroll
        for (int i2 = 0; i2 < 2; i2++) {
            int q = tid + i2 * 256;
            int k = q >> 5, nq = (q & 31) * 4;
            float4 v = *(const float4*)(Wo + (size_t)(k0 + k) * DM + n0b + nq);
            *(float4*)(Bs + k * 132 + nq) = v;
        }
        __syncthreads();
        #pragma unroll
        for (int kk = 0; kk < 16; kk++)
            micro8x8<20, 132>(As, Bs, ty * 8, tx * 8, kk, acc);
        __syncthreads();
    }

    #pragma unroll
    for (int i = 0; i < 8; i++) {
        int m = m0b + ty * 8 + i;
        float* row = out + (size_t)m * DM + n0b + tx * 8;
        #pragma unroll
        for (int j = 0; j < 4; j++) {
            u64 bb = *(const u64*)(bo + n0b + tx * 8 + 2 * j);
            *(u64*)(row + 2 * j) = add2(acc[i][j], bb);
        }
    }
}

// ---------------------------------------------------------------------------
extern "C" void kernel_launch(void* const* d_in, const int* in_sizes, int n_in,
                              void* d_out, int out_size)
{
    const float* x  = (const float*)d_in[0];
    const float* Wq = (const float*)d_in[1];
    const float* bq = (const float*)d_in[2];
    const float* Wk = (const float*)d_in[3];
    const float* bk = (const float*)d_in[4];
    const float* Wv = (const float*)d_in[5];
    const float* bv = (const float*)d_in[6];
    const float* Wo = (const float*)d_in[7];
    const float* bo = (const float*)d_in[8];
    const float* pe = (const float*)d_in[9];
    float* out = (float*)d_out;

    const int dsm_bytes = (128 * 68 + 64 * 132) * sizeof(float);  // 68608
    static int configured = 0;
    if (!configured) {
        cudaFuncSetAttribute(qk_gemm,  cudaFuncAttributeMaxDynamicSharedMemorySize, dsm_bytes);
        cudaFuncSetAttribute(qpe_gemm, cudaFuncAttributeMaxDynamicSharedMemorySize, dsm_bytes);
        configured = 1;
    }

    dim3 gqkv(DM / 128, NTOK / 128, 3);
    qkv_gemm<<<gqkv, 256>>>(x, Wq, bq, Wk, bk, Wv, bv);

    dim3 gqk(SEQ / 128, SEQ / 128, NHB);
    qk_gemm<<<gqk, 256, dsm_bytes>>>();
    qpe_gemm<<<gqk, 256, dsm_bytes>>>(pe);

    cope_softmax<<<NHB * SEQ, 128>>>();

    dim3 gav(SEQ / 256, NHB);
    av_gemm<<<gav, 256>>>();

    dim3 gout(DM / 128, NTOK / 128);
    out_gemm<<<gout, 256>>>(Wo, bo, out);
}

// round 6
// speedup vs baseline: 4.3180x; 1.8217x over previous
#include <cuda_runtime.h>
#include <cuda_bf16.h>
#include <math.h>
#include <stdint.h>

#define SEQ   1024
#define BATCH 4
#define DM    1024
#define NH    16
#define HD    64
#define NPOS  1000
#define NTOK  (SEQ*BATCH)   // 4096
#define NHB   (NH*BATCH)    // 64

#define APITCH 40           // bf16 elements per smem row (80B; conflict-free ldmatrix)

// ---------------------------------------------------------------------------
// Device scratch (no runtime allocation allowed)
// ---------------------------------------------------------------------------
__device__ float g_q[NHB*SEQ*HD];
__device__ float g_k[NHB*SEQ*HD];
__device__ float g_v[NHB*SEQ*HD];
__device__ float g_ctx[NTOK*DM];
__device__ float g_logits[(size_t)NHB*SEQ*SEQ];   // 268 MB; becomes attn probs
__device__ float g_li[(size_t)NHB*SEQ*SEQ];       // 268 MB; q·pos_emb (padded)
__device__ float g_wt[4*DM*DM];                   // WqT,WkT,WvT,WoT  [n][k]
__device__ float g_pet[SEQ*HD];                   // peT [n(1024 pad)][d]
__device__ float g_vt[NHB*HD*SEQ];                // vT  [hb][d][t]

// ---------------------------------------------------------------------------
// Warp-MMA helpers (baseline PTX only; no sm_103a features)
// ---------------------------------------------------------------------------
__device__ __forceinline__ uint32_t smem_u32(const void* p) {
    uint32_t a;
    asm("{ .reg .u64 t; cvta.to.shared.u64 t, %1; cvt.u32.u64 %0, t; }"
        : "=r"(a) : "l"(p));
    return a;
}
__device__ __forceinline__ void ldm4(uint32_t* r, uint32_t addr) {
    asm volatile("ldmatrix.sync.aligned.m8n8.x4.shared.b16 {%0,%1,%2,%3}, [%4];"
        : "=r"(r[0]), "=r"(r[1]), "=r"(r[2]), "=r"(r[3]) : "r"(addr));
}
__device__ __forceinline__ void mma_bf16(float* c, const uint32_t* a,
                                         const uint32_t* b) {
    asm volatile(
        "mma.sync.aligned.m16n8k16.row.col.f32.bf16.bf16.f32 "
        "{%0,%1,%2,%3}, {%4,%5,%6,%7}, {%8,%9}, {%0,%1,%2,%3};"
        : "+f"(c[0]), "+f"(c[1]), "+f"(c[2]), "+f"(c[3])
        : "r"(a[0]), "r"(a[1]), "r"(a[2]), "r"(a[3]), "r"(b[0]), "r"(b[1]));
}
__device__ __forceinline__ float sigmoidf_(float x) {
    return 1.0f / (1.0f + __expf(-x));
}

// ---------------------------------------------------------------------------
// Stage ROWSx32 f32 K-major tile -> bf16 hi/lo smem tiles (pitch APITCH)
// ---------------------------------------------------------------------------
template<int ROWS>
__device__ __forceinline__ void stage_bf16(const float* __restrict__ src, int ld,
                                           __nv_bfloat16* hi, __nv_bfloat16* lo,
                                           int tid)
{
    #pragma unroll
    for (int it = 0; it < ROWS * 8 / 256; it++) {
        int q = tid + it * 256;
        int row = q >> 3, kq = (q & 7) * 4;
        float4 v = *(const float4*)(src + (size_t)row * ld + kq);
        __nv_bfloat16 hx = __float2bfloat16_rn(v.x);
        __nv_bfloat16 hy = __float2bfloat16_rn(v.y);
        __nv_bfloat16 hz = __float2bfloat16_rn(v.z);
        __nv_bfloat16 hw = __float2bfloat16_rn(v.w);
        __nv_bfloat16 lx = __float2bfloat16_rn(v.x - __bfloat162float(hx));
        __nv_bfloat16 ly = __float2bfloat16_rn(v.y - __bfloat162float(hy));
        __nv_bfloat16 lz = __float2bfloat16_rn(v.z - __bfloat162float(hz));
        __nv_bfloat16 lw = __float2bfloat16_rn(v.w - __bfloat162float(hw));
        int o = row * APITCH + kq;
        *(__nv_bfloat162*)(hi + o)     = __nv_bfloat162(hx, hy);
        *(__nv_bfloat162*)(hi + o + 2) = __nv_bfloat162(hz, hw);
        *(__nv_bfloat162*)(lo + o)     = __nv_bfloat162(lx, ly);
        *(__nv_bfloat162*)(lo + o + 2) = __nv_bfloat162(lz, lw);
    }
}

// ---------------------------------------------------------------------------
// Core: C[128 x NTILE*16] += A[128 x ktot] · B[NTILE*16 x ktot]^T
// 8 warps as 4(m) x 2(n); warp tile 32 x NTILE*8. bf16 3-product split.
// ---------------------------------------------------------------------------
template<int NTILE>
__device__ __forceinline__ void mma_core(const float* A, int a_ld,
                                         const float* B, int b_ld, int ktot,
                                         float acc[2][NTILE][4],
                                         __nv_bfloat16* s)
{
    const int tid = threadIdx.x;
    const int warp = tid >> 5, lane = tid & 31;
    const int wm = warp >> 1, wn = warp & 1;
    constexpr int NROWS = NTILE * 16;

    __nv_bfloat16* Ahi = s;
    __nv_bfloat16* Alo = s + 128 * APITCH;
    __nv_bfloat16* Bhi = s + 2 * 128 * APITCH;
    __nv_bfloat16* Blo = Bhi + NROWS * APITCH;

    for (int k0 = 0; k0 < ktot; k0 += 32) {
        stage_bf16<128>(A + k0, a_ld, Ahi, Alo, tid);
        stage_bf16<NROWS>(B + k0, b_ld, Bhi, Blo, tid);
        __syncthreads();

        #pragma unroll
        for (int kk = 0; kk < 32; kk += 16) {
            uint32_t ah[2][4], al[2][4];
            #pragma unroll
            for (int tm = 0; tm < 2; tm++) {
                int r = wm * 32 + tm * 16 + ((lane >> 3) & 1) * 8 + (lane & 7);
                int c = kk + ((lane >> 4) & 1) * 8;
                uint32_t off = (uint32_t)(r * APITCH + c) * 2;
                ldm4(ah[tm], smem_u32(Ahi) + off);
                ldm4(al[tm], smem_u32(Alo) + off);
            }
            #pragma unroll
            for (int p = 0; p < NTILE / 2; p++) {
                uint32_t bh[4], bl[4];
                int n0 = wn * NTILE * 8 + p * 16;
                int r = n0 + ((lane >> 4) & 1) * 8 + (lane & 7);
                int c = kk + ((lane >> 3) & 1) * 8;
                uint32_t off = (uint32_t)(r * APITCH + c) * 2;
                ldm4(bh, smem_u32(Bhi) + off);
                ldm4(bl, smem_u32(Blo) + off);
                #pragma unroll
                for (int tm = 0; tm < 2; tm++) {
                    mma_bf16(acc[tm][2 * p],     ah[tm], bh);
                    mma_bf16(acc[tm][2 * p],     ah[tm], bl);
                    mma_bf16(acc[tm][2 * p],     al[tm], bh);
                    mma_bf16(acc[tm][2 * p + 1], ah[tm], bh + 2);
                    mma_bf16(acc[tm][2 * p + 1], ah[tm], bl + 2);
                    mma_bf16(acc[tm][2 * p + 1], al[tm], bh + 2);
                }
            }
        }
        __syncthreads();
    }
}

// ---------------------------------------------------------------------------
// Transpose kernels (block 256 = 32x8, smem 32x33)
// ---------------------------------------------------------------------------
__global__ __launch_bounds__(256) void transpose_w(
    const float* __restrict__ Wq, const float* __restrict__ Wk,
    const float* __restrict__ Wv, const float* __restrict__ Wo)
{
    __shared__ float t[32][33];
    const float* W = (blockIdx.z == 0) ? Wq : (blockIdx.z == 1) ? Wk
                   : (blockIdx.z == 2) ? Wv : Wo;
    float* out = g_wt + (size_t)blockIdx.z * DM * DM;
    int tx = threadIdx.x & 31, ty = threadIdx.x >> 5;
    int bx = blockIdx.x * 32, by = blockIdx.y * 32;
    #pragma unroll
    for (int j = 0; j < 4; j++)
        t[ty + 8 * j][tx] = W[(size_t)(by + ty + 8 * j) * DM + bx + tx];
    __syncthreads();
    #pragma unroll
    for (int j = 0; j < 4; j++)
        out[(size_t)(bx + ty + 8 * j) * DM + by + tx] = t[tx][ty + 8 * j];
}

__global__ __launch_bounds__(256) void transpose_pe(const float* __restrict__ pe)
{
    __shared__ float t[32][33];
    int tx = threadIdx.x & 31, ty = threadIdx.x >> 5;
    int bx = blockIdx.x * 32, by = blockIdx.y * 32;
    #pragma unroll
    for (int j = 0; j < 4; j++) {
        int d = by + ty + 8 * j, n = bx + tx;
        t[ty + 8 * j][tx] = (n < NPOS) ? pe[(size_t)d * NPOS + n] : 0.0f;
    }
    __syncthreads();
    #pragma unroll
    for (int j = 0; j < 4; j++)
        g_pet[(size_t)(bx + ty + 8 * j) * HD + by + tx] = t[tx][ty + 8 * j];
}

__global__ __launch_bounds__(256) void transpose_v()
{
    __shared__ float t[32][33];
    int hb = blockIdx.z;
    const float* V = g_v + (size_t)hb * SEQ * HD;
    float* out = g_vt + (size_t)hb * HD * SEQ;
    int tx = threadIdx.x & 31, ty = threadIdx.x >> 5;
    int bx = blockIdx.x * 32, by = blockIdx.y * 32;
    #pragma unroll
    for (int j = 0; j < 4; j++)
        t[ty + 8 * j][tx] = V[(size_t)(bx + ty + 8 * j) * HD + by + tx];
    __syncthreads();
    #pragma unroll
    for (int j = 0; j < 4; j++)
        out[(size_t)(by + ty + 8 * j) * SEQ + bx + tx] = t[tx][ty + 8 * j];
}

// ---------------------------------------------------------------------------
// K1: QKV projections (scatter to head layout, +bias)
// ---------------------------------------------------------------------------
__global__ __launch_bounds__(256) void qkv_mma(const float* __restrict__ x,
    const float* __restrict__ bq, const float* __restrict__ bk,
    const float* __restrict__ bv)
{
    __shared__ __nv_bfloat16 smem[4 * 128 * APITCH];
    const int tid = threadIdx.x;
    const int warp = tid >> 5, lane = tid & 31;
    const int wm = warp >> 1, wn = warp & 1;
    const int n0b = blockIdx.x * 128, m0b = blockIdx.y * 128, z = blockIdx.z;
    const float* bias = (z == 0) ? bq : (z == 1) ? bk : bv;
    float* out = (z == 0) ? g_q : (z == 1) ? g_k : g_v;

    float acc[2][8][4] = {};
    mma_core<8>(x + (size_t)m0b * DM, DM,
                g_wt + (size_t)z * DM * DM + (size_t)n0b * DM, DM,
                DM, acc, smem);

    #pragma unroll
    for (int tm = 0; tm < 2; tm++) {
        #pragma unroll
        for (int tn = 0; tn < 8; tn++) {
            int c = n0b + wn * 64 + tn * 8 + 2 * (lane & 3);
            int h = c >> 6, d = c & 63;
            float2 bb = *(const float2*)(bias + c);
            #pragma unroll
            for (int half = 0; half < 2; half++) {
                int m = m0b + wm * 32 + tm * 16 + (lane >> 2) + half * 8;
                int s = m >> 2, b_ = m & 3;
                float2 v;
                v.x = acc[tm][tn][2 * half + 0] + bb.x;
                v.y = acc[tm][tn][2 * half + 1] + bb.y;
                *(float2*)(out + ((size_t)(h * BATCH + b_) * SEQ + s) * HD + d) = v;
            }
        }
    }
}

// ---------------------------------------------------------------------------
// K2: logits = scale * Q K^T per (h,b)
// ---------------------------------------------------------------------------
__global__ __launch_bounds__(256) void qk_mma()
{
    __shared__ __nv_bfloat16 smem[4 * 128 * APITCH];
    const int tid = threadIdx.x;
    const int warp = tid >> 5, lane = tid & 31;
    const int wm = warp >> 1, wn = warp & 1;
    const int t0b = blockIdx.x * 128, m0b = blockIdx.y * 128, hb = blockIdx.z;

    float acc[2][8][4] = {};
    mma_core<8>(g_q + (size_t)hb * SEQ * HD + (size_t)m0b * HD, HD,
                g_k + (size_t)hb * SEQ * HD + (size_t)t0b * HD, HD,
                HD, acc, smem);

    float* Lb = g_logits + ((size_t)hb << 20);
    #pragma unroll
    for (int tm = 0; tm < 2; tm++) {
        #pragma unroll
        for (int tn = 0; tn < 8; tn++) {
            int c = t0b + wn * 64 + tn * 8 + 2 * (lane & 3);
            #pragma unroll
            for (int half = 0; half < 2; half++) {
                int m = m0b + wm * 32 + tm * 16 + (lane >> 2) + half * 8;
                float2 v;
                v.x = acc[tm][tn][2 * half + 0] * 0.125f;
                v.y = acc[tm][tn][2 * half + 1] * 0.125f;
                *(float2*)(Lb + (size_t)m * SEQ + c) = v;
            }
        }
    }
}

// ---------------------------------------------------------------------------
// K3: li = Q · pos_emb per (h,b)
// ---------------------------------------------------------------------------
__global__ __launch_bounds__(256) void qpe_mma()
{
    __shared__ __nv_bfloat16 smem[4 * 128 * APITCH];
    const int tid = threadIdx.x;
    const int warp = tid >> 5, lane = tid & 31;
    const int wm = warp >> 1, wn = warp & 1;
    const int n0b = blockIdx.x * 128, m0b = blockIdx.y * 128, hb = blockIdx.z;

    float acc[2][8][4] = {};
    mma_core<8>(g_q + (size_t)hb * SEQ * HD + (size_t)m0b * HD, HD,
                g_pet + (size_t)n0b * HD, HD,
                HD, acc, smem);

    float* Lb = g_li + ((size_t)hb << 20);
    #pragma unroll
    for (int tm = 0; tm < 2; tm++) {
        #pragma unroll
        for (int tn = 0; tn < 8; tn++) {
            int c = n0b + wn * 64 + tn * 8 + 2 * (lane & 3);
            #pragma unroll
            for (int half = 0; half < 2; half++) {
                int m = m0b + wm * 32 + tm * 16 + (lane >> 2) + half * 8;
                float2 v;
                v.x = acc[tm][tn][2 * half + 0];
                v.y = acc[tm][tn][2 * half + 1];
                *(float2*)(Lb + (size_t)m * SEQ + c) = v;
            }
        }
    }
}

// ---------------------------------------------------------------------------
// K4: per-row CoPE + softmax, in place on g_logits
// ---------------------------------------------------------------------------
__global__ __launch_bounds__(128) void cope_softmax()
{
    __shared__ __align__(16) float s_li[SEQ];
    __shared__ float s_w[4];
    __shared__ float s_m[4];
    __shared__ float s_s[4];

    const size_t row = blockIdx.x;
    float* L = g_logits + (row << 10);
    const float* li = g_li + (row << 10);
    const int tid = threadIdx.x;
    const int lane = tid & 31, warp = tid >> 5;

    #pragma unroll
    for (int i = 0; i < 2; i++)
        *(float4*)(s_li + tid * 4 + i * 512) = *(const float4*)(li + tid * 4 + i * 512);

    float l[8];
    {
        float4 a = *(const float4*)(L + tid * 8);
        float4 b = *(const float4*)(L + tid * 8 + 4);
        l[0] = a.x; l[1] = a.y; l[2] = a.z; l[3] = a.w;
        l[4] = b.x; l[5] = b.y; l[6] = b.z; l[7] = b.w;
    }

    float su[8];
    {
        float g = sigmoidf_(l[7]); su[7] = g;
        #pragma unroll
        for (int j = 6; j >= 0; j--) su[j] = su[j + 1] + sigmoidf_(l[j]);
    }
    float total = su[0];

    float v = total;
    #pragma unroll
    for (int off = 1; off < 32; off <<= 1) {
        float n = __shfl_down_sync(0xffffffffu, v, off);
        if (lane + off < 32) v += n;
    }
    if (lane == 0) s_w[warp] = v;
    __syncthreads();

    float basew = 0.f;
    #pragma unroll
    for (int w = 0; w < 4; w++) if (w > warp) basew += s_w[w];
    float base = basew + (v - total);

    #pragma unroll
    for (int j = 0; j < 8; j++) {
        float p = fminf(base + su[j], 999.0f);
        float pf = floorf(p);
        float w = p - pf;
        int fi = (int)pf;
        int ci = (int)ceilf(p);
        l[j] += s_li[ci] * w + s_li[fi] * (1.0f - w);
    }

    float m = l[0];
    #pragma unroll
    for (int j = 1; j < 8; j++) m = fmaxf(m, l[j]);
    #pragma unroll
    for (int off = 16; off; off >>= 1)
        m = fmaxf(m, __shfl_xor_sync(0xffffffffu, m, off));
    if (lane == 0) s_m[warp] = m;
    __syncthreads();
    m = fmaxf(fmaxf(s_m[0], s_m[1]), fmaxf(s_m[2], s_m[3]));

    float sum = 0.f;
    #pragma unroll
    for (int j = 0; j < 8; j++) { l[j] = __expf(l[j] - m); sum += l[j]; }
    #pragma unroll
    for (int off = 16; off; off >>= 1)
        sum += __shfl_xor_sync(0xffffffffu, sum, off);
    if (lane == 0) s_s[warp] = sum;
    __syncthreads();
    float inv = 1.0f / (s_s[0] + s_s[1] + s_s[2] + s_s[3]);

    float4 o0 = make_float4(l[0] * inv, l[1] * inv, l[2] * inv, l[3] * inv);
    float4 o1 = make_float4(l[4] * inv, l[5] * inv, l[6] * inv, l[7] * inv);
    *(float4*)(L + tid * 8) = o0;
    *(float4*)(L + tid * 8 + 4) = o1;
}

// ---------------------------------------------------------------------------
// K5: ctx = attn · V per (h,b). N = 64 (NTILE = 4)
// ---------------------------------------------------------------------------
__global__ __launch_bounds__(256) void av_mma()
{
    __shared__ __nv_bfloat16 smem[2 * 128 * APITCH + 2 * 64 * APITCH];
    const int tid = threadIdx.x;
    const int warp = tid >> 5, lane = tid & 31;
    const int wm = warp >> 1, wn = warp & 1;
    const int m0b = blockIdx.x * 128, hb = blockIdx.y;
    const int h = hb >> 2, b_ = hb & 3;

    float acc[2][4][4] = {};
    mma_core<4>(g_logits + ((size_t)hb << 20) + (size_t)m0b * SEQ, SEQ,
                g_vt + (size_t)hb * HD * SEQ, SEQ,
                SEQ, acc, smem);

    #pragma unroll
    for (int tm = 0; tm < 2; tm++) {
        #pragma unroll
        for (int tn = 0; tn < 4; tn++) {
            int d = wn * 32 + tn * 8 + 2 * (lane & 3);
            #pragma unroll
            for (int half = 0; half < 2; half++) {
                int s = m0b + wm * 32 + tm * 16 + (lane >> 2) + half * 8;
                float2 v;
                v.x = acc[tm][tn][2 * half + 0];
                v.y = acc[tm][tn][2 * half + 1];
                *(float2*)(g_ctx + ((size_t)s * BATCH + b_) * DM + h * HD + d) = v;
            }
        }
    }
}

// ---------------------------------------------------------------------------
// K6: output projection (+bias)
// ---------------------------------------------------------------------------
__global__ __launch_bounds__(256) void out_mma(const float* __restrict__ bo,
                                               float* __restrict__ out)
{
    __shared__ __nv_bfloat16 smem[4 * 128 * APITCH];
    const int tid = threadIdx.x;
    const int warp = tid >> 5, lane = tid & 31;
    const int wm = warp >> 1, wn = warp & 1;
    const int n0b = blockIdx.x * 128, m0b = blockIdx.y * 128;

    float acc[2][8][4] = {};
    mma_core<8>(g_ctx + (size_t)m0b * DM, DM,
                g_wt + (size_t)3 * DM * DM + (size_t)n0b * DM, DM,
                DM, acc, smem);

    #pragma unroll
    for (int tm = 0; tm < 2; tm++) {
        #pragma unroll
        for (int tn = 0; tn < 8; tn++) {
            int c = n0b + wn * 64 + tn * 8 + 2 * (lane & 3);
            float2 bb = *(const float2*)(bo + c);
            #pragma unroll
            for (int half = 0; half < 2; half++) {
                int m = m0b + wm * 32 + tm * 16 + (lane >> 2) + half * 8;
                float2 v;
                v.x = acc[tm][tn][2 * half + 0] + bb.x;
                v.y = acc[tm][tn][2 * half + 1] + bb.y;
                *(float2*)(out + (size_t)m * DM + c) = v;
            }
        }
    }
}

// ---------------------------------------------------------------------------
extern "C" void kernel_launch(void* const* d_in, const int* in_sizes, int n_in,
                              void* d_out, int out_size)
{
    const float* x  = (const float*)d_in[0];
    const float* Wq = (const float*)d_in[1];
    const float* bq = (const float*)d_in[2];
    const float* Wk = (const float*)d_in[3];
    const float* bk = (const float*)d_in[4];
    const float* Wv = (const float*)d_in[5];
    const float* bv = (const float*)d_in[6];
    const float* Wo = (const float*)d_in[7];
    const float* bo = (const float*)d_in[8];
    const float* pe = (const float*)d_in[9];
    float* out = (float*)d_out;

    transpose_w<<<dim3(DM / 32, DM / 32, 4), 256>>>(Wq, Wk, Wv, Wo);
    transpose_pe<<<dim3(SEQ / 32, HD / 32), 256>>>(pe);

    qkv_mma<<<dim3(DM / 128, NTOK / 128, 3), 256>>>(x, bq, bk, bv);

    transpose_v<<<dim3(SEQ / 32, HD / 32, NHB), 256>>>();

    qk_mma<<<dim3(SEQ / 128, SEQ / 128, NHB), 256>>>();
    qpe_mma<<<dim3(SEQ / 128, SEQ / 128, NHB), 256>>>();

    cope_softmax<<<NHB * SEQ, 128>>>();

    av_mma<<<dim3(SEQ / 128, NHB), 256>>>();

    out_mma<<<dim3(DM / 128, NTOK / 128), 256>>>(bo, out);
}

// round 7
// speedup vs baseline: 5.1948x; 1.2030x over previous
#include <cuda_runtime.h>
#include <cuda_bf16.h>
#include <cuda_fp16.h>
#include <math.h>
#include <stdint.h>

#define SEQ   1024
#define BATCH 4
#define DM    1024
#define NH    16
#define HD    64
#define NPOS  1000
#define NTOK  (SEQ*BATCH)   // 4096
#define NHB   (NH*BATCH)    // 64

typedef __nv_bfloat16 bf16;

// ---------------------------------------------------------------------------
// Device scratch (no runtime allocation allowed)
// ---------------------------------------------------------------------------
__device__ __align__(16) bf16 gx_h[NTOK*DM],  gx_l[NTOK*DM];
__device__ __align__(16) bf16 gw_h[4*DM*DM],  gw_l[4*DM*DM];
__device__ __align__(16) bf16 gpet_h[SEQ*HD], gpet_l[SEQ*HD];
__device__ __align__(16) bf16 gq_h[NHB*SEQ*HD], gq_l[NHB*SEQ*HD];
__device__ __align__(16) bf16 gk_h[NHB*SEQ*HD], gk_l[NHB*SEQ*HD];
__device__ __align__(16) float g_v[NHB*SEQ*HD];
__device__ __align__(16) bf16 gvt_h[NHB*HD*SEQ], gvt_l[NHB*HD*SEQ];
__device__ __align__(16) float g_logits[(size_t)NHB*SEQ*SEQ];   // 268 MB
__device__ __align__(16) __half g_li_h[(size_t)NHB*SEQ*SEQ];    // 134 MB
__device__ __align__(16) bf16 gp_h[(size_t)NHB*SEQ*SEQ];        // probs hi
__device__ __align__(16) bf16 gp_l[(size_t)NHB*SEQ*SEQ];        // probs lo
__device__ __align__(16) bf16 gctx_h[NTOK*DM], gctx_l[NTOK*DM];

// ---------------------------------------------------------------------------
// Helpers (baseline PTX only)
// ---------------------------------------------------------------------------
__device__ __forceinline__ uint32_t smem_u32(const void* p) {
    uint32_t a;
    asm("{ .reg .u64 t; cvta.to.shared.u64 t, %1; cvt.u32.u64 %0, t; }"
        : "=r"(a) : "l"(p));
    return a;
}
__device__ __forceinline__ void ldm4(uint32_t* r, uint32_t addr) {
    asm volatile("ldmatrix.sync.aligned.m8n8.x4.shared.b16 {%0,%1,%2,%3}, [%4];"
        : "=r"(r[0]), "=r"(r[1]), "=r"(r[2]), "=r"(r[3]) : "r"(addr));
}
__device__ __forceinline__ void mma_bf16(float* c, const uint32_t* a,
                                         const uint32_t* b) {
    asm volatile(
        "mma.sync.aligned.m16n8k16.row.col.f32.bf16.bf16.f32 "
        "{%0,%1,%2,%3}, {%4,%5,%6,%7}, {%8,%9}, {%0,%1,%2,%3};"
        : "+f"(c[0]), "+f"(c[1]), "+f"(c[2]), "+f"(c[3])
        : "r"(a[0]), "r"(a[1]), "r"(a[2]), "r"(a[3]), "r"(b[0]), "r"(b[1]));
}
__device__ __forceinline__ void cp16(uint32_t dst, const void* src) {
    asm volatile("cp.async.ca.shared.global [%0], [%1], 16;"
                 :: "r"(dst), "l"(src));
}
#define CP_COMMIT asm volatile("cp.async.commit_group;" ::: "memory")
#define CP_WAIT1  asm volatile("cp.async.wait_group 1;" ::: "memory")
#define CP_WAIT0  asm volatile("cp.async.wait_group 0;" ::: "memory")

__device__ __forceinline__ void split_bf16(float x, bf16& h, bf16& l) {
    h = __float2bfloat16_rn(x);
    l = __float2bfloat16_rn(x - __bfloat162float(h));
}
__device__ __forceinline__ float sigmoidf_(float x) {
    return 1.0f / (1.0f + __expf(-x));
}

// ---------------------------------------------------------------------------
// Stage ROWSx32 bf16 tile via cp.async. Smem rows pitch 80B (conflict-free
// ldmatrix), 4x16B chunks per row.
// ---------------------------------------------------------------------------
template<int ROWS>
__device__ __forceinline__ void stage_cp(const bf16* __restrict__ src, int ld,
                                         uint32_t smem_byte, int tid)
{
    #pragma unroll
    for (int it = 0; it < ROWS / 64; it++) {
        int q = tid + it * 256;
        int row = q >> 2, ch = q & 3;
        cp16(smem_byte + row * 80 + ch * 16, src + (size_t)row * ld + ch * 8);
    }
}

// ---------------------------------------------------------------------------
// Core: C[128 x NTILE*16] += A[128 x ktot] · B[NTILE*16 x ktot]^T
// Operands pre-split bf16 hi/lo. Double-buffered cp.async pipeline.
// 8 warps as 4(m) x 2(n); 3-product split accumulate in fp32.
// ---------------------------------------------------------------------------
template<int NTILE>
__device__ __forceinline__ void mma_core(
    const bf16* Ah, const bf16* Al, int a_ld,
    const bf16* Bh, const bf16* Bl, int b_ld,
    int ktot, float acc[2][NTILE][4], char* smem)
{
    const int tid = threadIdx.x;
    const int warp = tid >> 5, lane = tid & 31;
    const int wm = warp >> 1, wn = warp & 1;
    constexpr int NROWS = NTILE * 16;
    constexpr int TA = 128 * 80;
    constexpr int TB = NROWS * 80;
    constexpr int STAGE = 2 * TA + 2 * TB;
    const uint32_t sb = smem_u32(smem);
    const int nch = ktot / 32;

    // prologue: stage chunk 0 into buffer 0
    stage_cp<128>(Ah, a_ld, sb, tid);
    stage_cp<128>(Al, a_ld, sb + TA, tid);
    stage_cp<NROWS>(Bh, b_ld, sb + 2 * TA, tid);
    stage_cp<NROWS>(Bl, b_ld, sb + 2 * TA + TB, tid);
    CP_COMMIT;

    for (int c = 0; c < nch; c++) {
        const int cur = c & 1;
        if (c + 1 < nch) {
            uint32_t nb = sb + (cur ^ 1) * STAGE;
            stage_cp<128>(Ah + (c + 1) * 32, a_ld, nb, tid);
            stage_cp<128>(Al + (c + 1) * 32, a_ld, nb + TA, tid);
            stage_cp<NROWS>(Bh + (c + 1) * 32, b_ld, nb + 2 * TA, tid);
            stage_cp<NROWS>(Bl + (c + 1) * 32, b_ld, nb + 2 * TA + TB, tid);
            CP_COMMIT;
            CP_WAIT1;
        } else {
            CP_WAIT0;
        }
        __syncthreads();

        const uint32_t cb = sb + cur * STAGE;
        #pragma unroll
        for (int kk = 0; kk < 32; kk += 16) {
            uint32_t ah[2][4], al[2][4];
            #pragma unroll
            for (int tm = 0; tm < 2; tm++) {
                int r = wm * 32 + tm * 16 + ((lane >> 3) & 1) * 8 + (lane & 7);
                int cc = kk + ((lane >> 4) & 1) * 8;
                uint32_t off = (uint32_t)(r * 80 + cc * 2);
                ldm4(ah[tm], cb + off);
                ldm4(al[tm], cb + TA + off);
            }
            #pragma unroll
            for (int p = 0; p < NTILE / 2; p++) {
                uint32_t bh[4], bl[4];
                int r = wn * NTILE * 8 + p * 16 + ((lane >> 4) & 1) * 8 + (lane & 7);
                int cc = kk + ((lane >> 3) & 1) * 8;
                uint32_t off = (uint32_t)(r * 80 + cc * 2);
                ldm4(bh, cb + 2 * TA + off);
                ldm4(bl, cb + 2 * TA + TB + off);
                #pragma unroll
                for (int tm = 0; tm < 2; tm++) {
                    mma_bf16(acc[tm][2 * p],     ah[tm], bh);
                    mma_bf16(acc[tm][2 * p],     ah[tm], bl);
                    mma_bf16(acc[tm][2 * p],     al[tm], bh);
                    mma_bf16(acc[tm][2 * p + 1], ah[tm], bh + 2);
                    mma_bf16(acc[tm][2 * p + 1], ah[tm], bl + 2);
                    mma_bf16(acc[tm][2 * p + 1], al[tm], bh + 2);
                }
            }
        }
        __syncthreads();
    }
}

#define SMEM_N128 (2 * (2 * 128 * 80 + 2 * 128 * 80))   // 81920
#define SMEM_N64  (2 * (2 * 128 * 80 + 2 * 64 * 80))    // 61440

// ---------------------------------------------------------------------------
// Prologue conversion kernels
// ---------------------------------------------------------------------------
__global__ __launch_bounds__(256) void convert_x(const float* __restrict__ x)
{
    int i = (blockIdx.x * 256 + threadIdx.x) * 4;
    float4 v = *(const float4*)(x + i);
    bf16 h[4], l[4];
    split_bf16(v.x, h[0], l[0]); split_bf16(v.y, h[1], l[1]);
    split_bf16(v.z, h[2], l[2]); split_bf16(v.w, h[3], l[3]);
    *(__nv_bfloat162*)(gx_h + i)     = __nv_bfloat162(h[0], h[1]);
    *(__nv_bfloat162*)(gx_h + i + 2) = __nv_bfloat162(h[2], h[3]);
    *(__nv_bfloat162*)(gx_l + i)     = __nv_bfloat162(l[0], l[1]);
    *(__nv_bfloat162*)(gx_l + i + 2) = __nv_bfloat162(l[2], l[3]);
}

__global__ __launch_bounds__(256) void transpose_w(
    const float* __restrict__ Wq, const float* __restrict__ Wk,
    const float* __restrict__ Wv, const float* __restrict__ Wo)
{
    __shared__ float t[32][33];
    const float* W = (blockIdx.z == 0) ? Wq : (blockIdx.z == 1) ? Wk
                   : (blockIdx.z == 2) ? Wv : Wo;
    size_t base = (size_t)blockIdx.z * DM * DM;
    int tx = threadIdx.x & 31, ty = threadIdx.x >> 5;
    int bx = blockIdx.x * 32, by = blockIdx.y * 32;
    #pragma unroll
    for (int j = 0; j < 4; j++)
        t[ty + 8 * j][tx] = W[(size_t)(by + ty + 8 * j) * DM + bx + tx];
    __syncthreads();
    #pragma unroll
    for (int j = 0; j < 4; j++) {
        bf16 h, l;
        split_bf16(t[tx][ty + 8 * j], h, l);
        size_t o = base + (size_t)(bx + ty + 8 * j) * DM + by + tx;
        gw_h[o] = h; gw_l[o] = l;
    }
}

__global__ __launch_bounds__(256) void transpose_pe(const float* __restrict__ pe)
{
    __shared__ float t[32][33];
    int tx = threadIdx.x & 31, ty = threadIdx.x >> 5;
    int bx = blockIdx.x * 32, by = blockIdx.y * 32;
    #pragma unroll
    for (int j = 0; j < 4; j++) {
        int d = by + ty + 8 * j, n = bx + tx;
        t[ty + 8 * j][tx] = (n < NPOS) ? pe[(size_t)d * NPOS + n] : 0.0f;
    }
    __syncthreads();
    #pragma unroll
    for (int j = 0; j < 4; j++) {
        bf16 h, l;
        split_bf16(t[tx][ty + 8 * j], h, l);
        size_t o = (size_t)(bx + ty + 8 * j) * HD + by + tx;
        gpet_h[o] = h; gpet_l[o] = l;
    }
}

__global__ __launch_bounds__(256) void transpose_v()
{
    __shared__ float t[32][33];
    int hb = blockIdx.z;
    const float* V = g_v + (size_t)hb * SEQ * HD;
    size_t base = (size_t)hb * HD * SEQ;
    int tx = threadIdx.x & 31, ty = threadIdx.x >> 5;
    int bx = blockIdx.x * 32, by = blockIdx.y * 32;   // bx: t, by: d
    #pragma unroll
    for (int j = 0; j < 4; j++)
        t[ty + 8 * j][tx] = V[(size_t)(bx + ty + 8 * j) * HD + by + tx];
    __syncthreads();
    #pragma unroll
    for (int j = 0; j < 4; j++) {
        bf16 h, l;
        split_bf16(t[tx][ty + 8 * j], h, l);
        size_t o = base + (size_t)(by + ty + 8 * j) * SEQ + bx + tx;
        gvt_h[o] = h; gvt_l[o] = l;
    }
}

// ---------------------------------------------------------------------------
// K1: QKV projections. q,k written pre-split; v written f32.
// ---------------------------------------------------------------------------
__global__ __launch_bounds__(256, 2) void qkv_mma(
    const float* __restrict__ bq, const float* __restrict__ bk,
    const float* __restrict__ bv)
{
    extern __shared__ char smem[];
    const int tid = threadIdx.x;
    const int warp = tid >> 5, lane = tid & 31;
    const int wm = warp >> 1, wn = warp & 1;
    const int n0b = blockIdx.x * 128, m0b = blockIdx.y * 128, z = blockIdx.z;
    const float* bias = (z == 0) ? bq : (z == 1) ? bk : bv;

    float acc[2][8][4] = {};
    mma_core<8>(gx_h + (size_t)m0b * DM, gx_l + (size_t)m0b * DM, DM,
                gw_h + (size_t)z * DM * DM + (size_t)n0b * DM,
                gw_l + (size_t)z * DM * DM + (size_t)n0b * DM, DM,
                DM, acc, smem);

    #pragma unroll
    for (int tm = 0; tm < 2; tm++) {
        #pragma unroll
        for (int tn = 0; tn < 8; tn++) {
            int c = n0b + wn * 64 + tn * 8 + 2 * (lane & 3);
            int h = c >> 6, d = c & 63;
            float2 bb = *(const float2*)(bias + c);
            #pragma unroll
            for (int half = 0; half < 2; half++) {
                int m = m0b + wm * 32 + tm * 16 + (lane >> 2) + half * 8;
                int s = m >> 2, b_ = m & 3;
                float vx = acc[tm][tn][2 * half + 0] + bb.x;
                float vy = acc[tm][tn][2 * half + 1] + bb.y;
                size_t o = ((size_t)(h * BATCH + b_) * SEQ + s) * HD + d;
                if (z == 2) {
                    *(float2*)(g_v + o) = make_float2(vx, vy);
                } else {
                    bf16 hx, lx, hy, ly;
                    split_bf16(vx, hx, lx);
                    split_bf16(vy, hy, ly);
                    if (z == 0) {
                        *(__nv_bfloat162*)(gq_h + o) = __nv_bfloat162(hx, hy);
                        *(__nv_bfloat162*)(gq_l + o) = __nv_bfloat162(lx, ly);
                    } else {
                        *(__nv_bfloat162*)(gk_h + o) = __nv_bfloat162(hx, hy);
                        *(__nv_bfloat162*)(gk_l + o) = __nv_bfloat162(lx, ly);
                    }
                }
            }
        }
    }
}

// ---------------------------------------------------------------------------
// K2: logits = scale * Q K^T per (h,b)
// ---------------------------------------------------------------------------
__global__ __launch_bounds__(256, 2) void qk_mma()
{
    extern __shared__ char smem[];
    const int tid = threadIdx.x;
    const int warp = tid >> 5, lane = tid & 31;
    const int wm = warp >> 1, wn = warp & 1;
    const int t0b = blockIdx.x * 128, m0b = blockIdx.y * 128, hb = blockIdx.z;
    const size_t qo = (size_t)hb * SEQ * HD + (size_t)m0b * HD;
    const size_t ko = (size_t)hb * SEQ * HD + (size_t)t0b * HD;

    float acc[2][8][4] = {};
    mma_core<8>(gq_h + qo, gq_l + qo, HD, gk_h + ko, gk_l + ko, HD,
                HD, acc, smem);

    float* Lb = g_logits + ((size_t)hb << 20);
    #pragma unroll
    for (int tm = 0; tm < 2; tm++) {
        #pragma unroll
        for (int tn = 0; tn < 8; tn++) {
            int c = t0b + wn * 64 + tn * 8 + 2 * (lane & 3);
            #pragma unroll
            for (int half = 0; half < 2; half++) {
                int m = m0b + wm * 32 + tm * 16 + (lane >> 2) + half * 8;
                float2 v;
                v.x = acc[tm][tn][2 * half + 0] * 0.125f;
                v.y = acc[tm][tn][2 * half + 1] * 0.125f;
                *(float2*)(Lb + (size_t)m * SEQ + c) = v;
            }
        }
    }
}

// ---------------------------------------------------------------------------
// K3: li = Q · pos_emb per (h,b) -> fp16
// ---------------------------------------------------------------------------
__global__ __launch_bounds__(256, 2) void qpe_mma()
{
    extern __shared__ char smem[];
    const int tid = threadIdx.x;
    const int warp = tid >> 5, lane = tid & 31;
    const int wm = warp >> 1, wn = warp & 1;
    const int n0b = blockIdx.x * 128, m0b = blockIdx.y * 128, hb = blockIdx.z;
    const size_t qo = (size_t)hb * SEQ * HD + (size_t)m0b * HD;

    float acc[2][8][4] = {};
    mma_core<8>(gq_h + qo, gq_l + qo, HD,
                gpet_h + (size_t)n0b * HD, gpet_l + (size_t)n0b * HD, HD,
                HD, acc, smem);

    __half* Lb = g_li_h + ((size_t)hb << 20);
    #pragma unroll
    for (int tm = 0; tm < 2; tm++) {
        #pragma unroll
        for (int tn = 0; tn < 8; tn++) {
            int c = n0b + wn * 64 + tn * 8 + 2 * (lane & 3);
            #pragma unroll
            for (int half = 0; half < 2; half++) {
                int m = m0b + wm * 32 + tm * 16 + (lane >> 2) + half * 8;
                __half2 v = __floats2half2_rn(acc[tm][tn][2 * half + 0],
                                              acc[tm][tn][2 * half + 1]);
                *(__half2*)(Lb + (size_t)m * SEQ + c) = v;
            }
        }
    }
}

// ---------------------------------------------------------------------------
// K4: per-row CoPE + softmax; probs written pre-split bf16 hi/lo.
// ---------------------------------------------------------------------------
__global__ __launch_bounds__(128) void cope_softmax()
{
    __shared__ __align__(16) float s_li[SEQ];
    __shared__ float s_w[4];
    __shared__ float s_m[4];
    __shared__ float s_s[4];

    const size_t row = blockIdx.x;
    float* L = g_logits + (row << 10);
    const __half* li = g_li_h + (row << 10);
    const int tid = threadIdx.x;
    const int lane = tid & 31, warp = tid >> 5;

    // stage li row (8 halves per thread)
    {
        uint4 u = *(const uint4*)(li + tid * 8);
        const __half2* hp = (const __half2*)&u;
        #pragma unroll
        for (int i = 0; i < 4; i++) {
            float2 f = __half22float2(hp[i]);
            s_li[tid * 8 + 2 * i + 0] = f.x;
            s_li[tid * 8 + 2 * i + 1] = f.y;
        }
    }

    float l[8];
    {
        float4 a = *(const float4*)(L + tid * 8);
        float4 b = *(const float4*)(L + tid * 8 + 4);
        l[0] = a.x; l[1] = a.y; l[2] = a.z; l[3] = a.w;
        l[4] = b.x; l[5] = b.y; l[6] = b.z; l[7] = b.w;
    }

    float su[8];
    {
        float g = sigmoidf_(l[7]); su[7] = g;
        #pragma unroll
        for (int j = 6; j >= 0; j--) su[j] = su[j + 1] + sigmoidf_(l[j]);
    }
    float total = su[0];

    float v = total;
    #pragma unroll
    for (int off = 1; off < 32; off <<= 1) {
        float n = __shfl_down_sync(0xffffffffu, v, off);
        if (lane + off < 32) v += n;
    }
    if (lane == 0) s_w[warp] = v;
    __syncthreads();

    float basew = 0.f;
    #pragma unroll
    for (int w = 0; w < 4; w++) if (w > warp) basew += s_w[w];
    float base = basew + (v - total);

    #pragma unroll
    for (int j = 0; j < 8; j++) {
        float p = fminf(base + su[j], 999.0f);
        float pf = floorf(p);
        float w = p - pf;
        int fi = (int)pf;
        int ci = (int)ceilf(p);
        l[j] += s_li[ci] * w + s_li[fi] * (1.0f - w);
    }

    float m = l[0];
    #pragma unroll
    for (int j = 1; j < 8; j++) m = fmaxf(m, l[j]);
    #pragma unroll
    for (int off = 16; off; off >>= 1)
        m = fmaxf(m, __shfl_xor_sync(0xffffffffu, m, off));
    if (lane == 0) s_m[warp] = m;
    __syncthreads();
    m = fmaxf(fmaxf(s_m[0], s_m[1]), fmaxf(s_m[2], s_m[3]));

    float sum = 0.f;
    #pragma unroll
    for (int j = 0; j < 8; j++) { l[j] = __expf(l[j] - m); sum += l[j]; }
    #pragma unroll
    for (int off = 16; off; off >>= 1)
        sum += __shfl_xor_sync(0xffffffffu, sum, off);
    if (lane == 0) s_s[warp] = sum;
    __syncthreads();
    float inv = 1.0f / (s_s[0] + s_s[1] + s_s[2] + s_s[3]);

    union { bf16 a[8]; uint4 u; } ph, pl;
    #pragma unroll
    for (int j = 0; j < 8; j++)
        split_bf16(l[j] * inv, ph.a[j], pl.a[j]);
    *(uint4*)(gp_h + (row << 10) + tid * 8) = ph.u;
    *(uint4*)(gp_l + (row << 10) + tid * 8) = pl.u;
}

// ---------------------------------------------------------------------------
// K5: ctx = attn · V per (h,b). N = 64; ctx written pre-split bf16.
// ---------------------------------------------------------------------------
__global__ __launch_bounds__(256, 2) void av_mma()
{
    extern __shared__ char smem[];
    const int tid = threadIdx.x;
    const int warp = tid >> 5, lane = tid & 31;
    const int wm = warp >> 1, wn = warp & 1;
    const int m0b = blockIdx.x * 128, hb = blockIdx.y;
    const int h = hb >> 2, b_ = hb & 3;
    const size_t po = ((size_t)hb << 20) + (size_t)m0b * SEQ;
    const size_t vo = (size_t)hb * HD * SEQ;

    float acc[2][4][4] = {};
    mma_core<4>(gp_h + po, gp_l + po, SEQ, gvt_h + vo, gvt_l + vo, SEQ,
                SEQ, acc, smem);

    #pragma unroll
    for (int tm = 0; tm < 2; tm++) {
        #pragma unroll
        for (int tn = 0; tn < 4; tn++) {
            int d = wn * 32 + tn * 8 + 2 * (lane & 3);
            #pragma unroll
            for (int half = 0; half < 2; half++) {
                int s = m0b + wm * 32 + tm * 16 + (lane >> 2) + half * 8;
                size_t o = ((size_t)s * BATCH + b_) * DM + h * HD + d;
                bf16 hx, lx, hy, ly;
                split_bf16(acc[tm][tn][2 * half + 0], hx, lx);
                split_bf16(acc[tm][tn][2 * half + 1], hy, ly);
                *(__nv_bfloat162*)(gctx_h + o) = __nv_bfloat162(hx, hy);
                *(__nv_bfloat162*)(gctx_l + o) = __nv_bfloat162(lx, ly);
            }
        }
    }
}

// ---------------------------------------------------------------------------
// K6: output projection (+bias)
// ---------------------------------------------------------------------------
__global__ __launch_bounds__(256, 2) void out_mma(const float* __restrict__ bo,
                                                  float* __restrict__ out)
{
    extern __shared__ char smem[];
    const int tid = threadIdx.x;
    const int warp = tid >> 5, lane = tid & 31;
    const int wm = warp >> 1, wn = warp & 1;
    const int n0b = blockIdx.x * 128, m0b = blockIdx.y * 128;

    float acc[2][8][4] = {};
    mma_core<8>(gctx_h + (size_t)m0b * DM, gctx_l + (size_t)m0b * DM, DM,
                gw_h + (size_t)3 * DM * DM + (size_t)n0b * DM,
                gw_l + (size_t)3 * DM * DM + (size_t)n0b * DM, DM,
                DM, acc, smem);

    #pragma unroll
    for (int tm = 0; tm < 2; tm++) {
        #pragma unroll
        for (int tn = 0; tn < 8; tn++) {
            int c = n0b + wn * 64 + tn * 8 + 2 * (lane & 3);
            float2 bb = *(const float2*)(bo + c);
            #pragma unroll
            for (int half = 0; half < 2; half++) {
                int m = m0b + wm * 32 + tm * 16 + (lane >> 2) + half * 8;
                float2 v;
                v.x = acc[tm][tn][2 * half + 0] + bb.x;
                v.y = acc[tm][tn][2 * half + 1] + bb.y;
                *(float2*)(out + (size_t)m * DM + c) = v;
            }
        }
    }
}

// ---------------------------------------------------------------------------
extern "C" void kernel_launch(void* const* d_in, const int* in_sizes, int n_in,
                              void* d_out, int out_size)
{
    const float* x  = (const float*)d_in[0];
    const float* Wq = (const float*)d_in[1];
    const float* bq = (const float*)d_in[2];
    const float* Wk = (const float*)d_in[3];
    const float* bk = (const float*)d_in[4];
    const float* Wv = (const float*)d_in[5];
    const float* bv = (const float*)d_in[6];
    const float* Wo = (const float*)d_in[7];
    const float* bo = (const float*)d_in[8];
    const float* pe = (const float*)d_in[9];
    float* out = (float*)d_out;

    cudaFuncSetAttribute(qkv_mma, cudaFuncAttributeMaxDynamicSharedMemorySize, SMEM_N128);
    cudaFuncSetAttribute(qk_mma,  cudaFuncAttributeMaxDynamicSharedMemorySize, SMEM_N128);
    cudaFuncSetAttribute(qpe_mma, cudaFuncAttributeMaxDynamicSharedMemorySize, SMEM_N128);
    cudaFuncSetAttribute(out_mma, cudaFuncAttributeMaxDynamicSharedMemorySize, SMEM_N128);
    cudaFuncSetAttribute(av_mma,  cudaFuncAttributeMaxDynamicSharedMemorySize, SMEM_N64);

    convert_x<<<NTOK * DM / 1024, 256>>>(x);
    transpose_w<<<dim3(DM / 32, DM / 32, 4), 256>>>(Wq, Wk, Wv, Wo);
    transpose_pe<<<dim3(SEQ / 32, HD / 32), 256>>>(pe);

    qkv_mma<<<dim3(DM / 128, NTOK / 128, 3), 256, SMEM_N128>>>(bq, bk, bv);

    transpose_v<<<dim3(SEQ / 32, HD / 32, NHB), 256>>>();

    qk_mma<<<dim3(SEQ / 128, SEQ / 128, NHB), 256, SMEM_N128>>>();
    qpe_mma<<<dim3(SEQ / 128, SEQ / 128, NHB), 256, SMEM_N128>>>();

    cope_softmax<<<NHB * SEQ, 128>>>();

    av_mma<<<dim3(SEQ / 128, NHB), 256, SMEM_N64>>>();

    out_mma<<<dim3(DM / 128, NTOK / 128), 256, SMEM_N128>>>(bo, out);
}

// round 8
// speedup vs baseline: 8.8262x; 1.6991x over previous
#include <cuda_runtime.h>
#include <cuda_fp16.h>
#include <math.h>
#include <stdint.h>

#define SEQ   1024
#define BATCH 4
#define DM    1024
#define NH    16
#define HD    64
#define NPOS  1000
#define NTOK  (SEQ*BATCH)   // 4096
#define NHB   (NH*BATCH)    // 64

// ---------------------------------------------------------------------------
// Device scratch (no runtime allocation allowed) — all fp16
// ---------------------------------------------------------------------------
__device__ __align__(16) __half gx[NTOK*DM];
__device__ __align__(16) __half gw[4*DM*DM];          // WqT,WkT,WvT,WoT [n][k]
__device__ __align__(16) __half gpet[SEQ*HD];         // peT [n pad][d]
__device__ __align__(16) __half gq[NHB*SEQ*HD];
__device__ __align__(16) __half gk[NHB*SEQ*HD];
__device__ __align__(16) __half gv[NHB*SEQ*HD];
__device__ __align__(16) __half gvt[NHB*HD*SEQ];      // vT [hb][d][t]
__device__ __align__(16) __half g_logits[(size_t)NHB*SEQ*SEQ];  // 134 MB
__device__ __align__(16) __half g_li[(size_t)NHB*SEQ*SEQ];      // 134 MB
__device__ __align__(16) __half gp[(size_t)NHB*SEQ*SEQ];        // probs
__device__ __align__(16) __half gctx[NTOK*DM];

// ---------------------------------------------------------------------------
// Helpers (baseline PTX only)
// ---------------------------------------------------------------------------
__device__ __forceinline__ uint32_t smem_u32(const void* p) {
    uint32_t a;
    asm("{ .reg .u64 t; cvta.to.shared.u64 t, %1; cvt.u32.u64 %0, t; }"
        : "=r"(a) : "l"(p));
    return a;
}
__device__ __forceinline__ void ldm4(uint32_t* r, uint32_t addr) {
    asm volatile("ldmatrix.sync.aligned.m8n8.x4.shared.b16 {%0,%1,%2,%3}, [%4];"
        : "=r"(r[0]), "=r"(r[1]), "=r"(r[2]), "=r"(r[3]) : "r"(addr));
}
__device__ __forceinline__ void mma_f16(float* c, const uint32_t* a,
                                        const uint32_t* b) {
    asm volatile(
        "mma.sync.aligned.m16n8k16.row.col.f32.f16.f16.f32 "
        "{%0,%1,%2,%3}, {%4,%5,%6,%7}, {%8,%9}, {%0,%1,%2,%3};"
        : "+f"(c[0]), "+f"(c[1]), "+f"(c[2]), "+f"(c[3])
        : "r"(a[0]), "r"(a[1]), "r"(a[2]), "r"(a[3]), "r"(b[0]), "r"(b[1]));
}
__device__ __forceinline__ void cp16(uint32_t dst, const void* src) {
    asm volatile("cp.async.ca.shared.global [%0], [%1], 16;"
                 :: "r"(dst), "l"(src));
}
#define CP_COMMIT asm volatile("cp.async.commit_group;" ::: "memory")
#define CP_WAIT1  asm volatile("cp.async.wait_group 1;" ::: "memory")
#define CP_WAIT0  asm volatile("cp.async.wait_group 0;" ::: "memory")

__device__ __forceinline__ float sigmoidf_(float x) {
    return 1.0f / (1.0f + __expf(-x));
}

// ---------------------------------------------------------------------------
// Stage ROWSx32 fp16 K-major tile via cp.async; pitch 80B (conflict-free
// ldmatrix), 4x16B chunks per row.
// ---------------------------------------------------------------------------
template<int ROWS>
__device__ __forceinline__ void stage_cp(const __half* __restrict__ src, int ld,
                                         uint32_t smem_byte, int tid)
{
    #pragma unroll
    for (int it = 0; it < ROWS / 64; it++) {
        int q = tid + it * 256;
        int row = q >> 2, ch = q & 3;
        cp16(smem_byte + row * 80 + ch * 16, src + (size_t)row * ld + ch * 8);
    }
}

// ---------------------------------------------------------------------------
// Core: C[128 x NTILE*16] += A[128 x ktot] · B[NTILE*16 x ktot]^T
// fp16 single-product, fp32 accum. Double-buffered cp.async pipeline.
// 8 warps as 4(m) x 2(n).
// ---------------------------------------------------------------------------
template<int NTILE>
__device__ __forceinline__ void mma_core(
    const __half* A, int a_ld, const __half* B, int b_ld,
    int ktot, float acc[2][NTILE][4], char* smem)
{
    const int tid = threadIdx.x;
    const int warp = tid >> 5, lane = tid & 31;
    const int wm = warp >> 1, wn = warp & 1;
    constexpr int NROWS = NTILE * 16;
    constexpr int TA = 128 * 80;
    constexpr int TB = NROWS * 80;
    constexpr int STAGE = TA + TB;
    const uint32_t sb = smem_u32(smem);
    const int nch = ktot / 32;

    stage_cp<128>(A, a_ld, sb, tid);
    stage_cp<NROWS>(B, b_ld, sb + TA, tid);
    CP_COMMIT;

    for (int c = 0; c < nch; c++) {
        const int cur = c & 1;
        if (c + 1 < nch) {
            uint32_t nb = sb + (cur ^ 1) * STAGE;
            stage_cp<128>(A + (c + 1) * 32, a_ld, nb, tid);
            stage_cp<NROWS>(B + (c + 1) * 32, b_ld, nb + TA, tid);
            CP_COMMIT;
            CP_WAIT1;
        } else {
            CP_WAIT0;
        }
        __syncthreads();

        const uint32_t cb = sb + cur * STAGE;
        #pragma unroll
        for (int kk = 0; kk < 32; kk += 16) {
            uint32_t ah[2][4];
            #pragma unroll
            for (int tm = 0; tm < 2; tm++) {
                int r = wm * 32 + tm * 16 + ((lane >> 3) & 1) * 8 + (lane & 7);
                int cc = kk + ((lane >> 4) & 1) * 8;
                ldm4(ah[tm], cb + (uint32_t)(r * 80 + cc * 2));
            }
            #pragma unroll
            for (int p = 0; p < NTILE / 2; p++) {
                uint32_t bh[4];
                int r = wn * NTILE * 8 + p * 16 + ((lane >> 4) & 1) * 8 + (lane & 7);
                int cc = kk + ((lane >> 3) & 1) * 8;
                ldm4(bh, cb + TA + (uint32_t)(r * 80 + cc * 2));
                #pragma unroll
                for (int tm = 0; tm < 2; tm++) {
                    mma_f16(acc[tm][2 * p],     ah[tm], bh);
                    mma_f16(acc[tm][2 * p + 1], ah[tm], bh + 2);
                }
            }
        }
        __syncthreads();
    }
}

#define SMEM_N128 (2 * (128 * 80 + 128 * 80))   // 40960
#define SMEM_N64  (2 * (128 * 80 + 64 * 80))    // 30720

// ---------------------------------------------------------------------------
// Prologue conversion kernels
// ---------------------------------------------------------------------------
__global__ __launch_bounds__(256) void convert_x(const float* __restrict__ x)
{
    int i = (blockIdx.x * 256 + threadIdx.x) * 4;
    float4 v = *(const float4*)(x + i);
    *(__half2*)(gx + i)     = __floats2half2_rn(v.x, v.y);
    *(__half2*)(gx + i + 2) = __floats2half2_rn(v.z, v.w);
}

__global__ __launch_bounds__(256) void transpose_w(
    const float* __restrict__ Wq, const float* __restrict__ Wk,
    const float* __restrict__ Wv, const float* __restrict__ Wo)
{
    __shared__ float t[32][33];
    const float* W = (blockIdx.z == 0) ? Wq : (blockIdx.z == 1) ? Wk
                   : (blockIdx.z == 2) ? Wv : Wo;
    size_t base = (size_t)blockIdx.z * DM * DM;
    int tx = threadIdx.x & 31, ty = threadIdx.x >> 5;
    int bx = blockIdx.x * 32, by = blockIdx.y * 32;
    #pragma unroll
    for (int j = 0; j < 4; j++)
        t[ty + 8 * j][tx] = W[(size_t)(by + ty + 8 * j) * DM + bx + tx];
    __syncthreads();
    #pragma unroll
    for (int j = 0; j < 4; j++)
        gw[base + (size_t)(bx + ty + 8 * j) * DM + by + tx] =
            __float2half_rn(t[tx][ty + 8 * j]);
}

__global__ __launch_bounds__(256) void transpose_pe(const float* __restrict__ pe)
{
    __shared__ float t[32][33];
    int tx = threadIdx.x & 31, ty = threadIdx.x >> 5;
    int bx = blockIdx.x * 32, by = blockIdx.y * 32;
    #pragma unroll
    for (int j = 0; j < 4; j++) {
        int d = by + ty + 8 * j, n = bx + tx;
        t[ty + 8 * j][tx] = (n < NPOS) ? pe[(size_t)d * NPOS + n] : 0.0f;
    }
    __syncthreads();
    #pragma unroll
    for (int j = 0; j < 4; j++)
        gpet[(size_t)(bx + ty + 8 * j) * HD + by + tx] =
            __float2half_rn(t[tx][ty + 8 * j]);
}

__global__ __launch_bounds__(256) void transpose_v()
{
    __shared__ __half t[32][40];
    int hb = blockIdx.z;
    const __half* V = gv + (size_t)hb * SEQ * HD;
    size_t base = (size_t)hb * HD * SEQ;
    int tx = threadIdx.x & 31, ty = threadIdx.x >> 5;
    int bx = blockIdx.x * 32, by = blockIdx.y * 32;   // bx: t, by: d
    #pragma unroll
    for (int j = 0; j < 4; j++)
        t[ty + 8 * j][tx] = V[(size_t)(bx + ty + 8 * j) * HD + by + tx];
    __syncthreads();
    #pragma unroll
    for (int j = 0; j < 4; j++)
        gvt[base + (size_t)(by + ty + 8 * j) * SEQ + bx + tx] = t[tx][ty + 8 * j];
}

// ---------------------------------------------------------------------------
// K1: QKV projections (scatter to head layout, +bias) -> fp16 q,k,v
// ---------------------------------------------------------------------------
__global__ __launch_bounds__(256, 2) void qkv_mma(
    const float* __restrict__ bq, const float* __restrict__ bk,
    const float* __restrict__ bv)
{
    extern __shared__ char smem[];
    const int tid = threadIdx.x;
    const int warp = tid >> 5, lane = tid & 31;
    const int wm = warp >> 1, wn = warp & 1;
    const int n0b = blockIdx.x * 128, m0b = blockIdx.y * 128, z = blockIdx.z;
    const float* bias = (z == 0) ? bq : (z == 1) ? bk : bv;
    __half* out = (z == 0) ? gq : (z == 1) ? gk : gv;

    float acc[2][8][4] = {};
    mma_core<8>(gx + (size_t)m0b * DM, DM,
                gw + (size_t)z * DM * DM + (size_t)n0b * DM, DM,
                DM, acc, smem);

    #pragma unroll
    for (int tm = 0; tm < 2; tm++) {
        #pragma unroll
        for (int tn = 0; tn < 8; tn++) {
            int c = n0b + wn * 64 + tn * 8 + 2 * (lane & 3);
            int h = c >> 6, d = c & 63;
            float2 bb = *(const float2*)(bias + c);
            #pragma unroll
            for (int half_ = 0; half_ < 2; half_++) {
                int m = m0b + wm * 32 + tm * 16 + (lane >> 2) + half_ * 8;
                int s = m >> 2, b_ = m & 3;
                __half2 v = __floats2half2_rn(acc[tm][tn][2 * half_ + 0] + bb.x,
                                              acc[tm][tn][2 * half_ + 1] + bb.y);
                *(__half2*)(out + ((size_t)(h * BATCH + b_) * SEQ + s) * HD + d) = v;
            }
        }
    }
}

// ---------------------------------------------------------------------------
// K2: logits = scale * Q K^T per (h,b) -> fp16
// ---------------------------------------------------------------------------
__global__ __launch_bounds__(256, 2) void qk_mma()
{
    extern __shared__ char smem[];
    const int tid = threadIdx.x;
    const int warp = tid >> 5, lane = tid & 31;
    const int wm = warp >> 1, wn = warp & 1;
    const int t0b = blockIdx.x * 128, m0b = blockIdx.y * 128, hb = blockIdx.z;

    float acc[2][8][4] = {};
    mma_core<8>(gq + (size_t)hb * SEQ * HD + (size_t)m0b * HD, HD,
                gk + (size_t)hb * SEQ * HD + (size_t)t0b * HD, HD,
                HD, acc, smem);

    __half* Lb = g_logits + ((size_t)hb << 20);
    #pragma unroll
    for (int tm = 0; tm < 2; tm++) {
        #pragma unroll
        for (int tn = 0; tn < 8; tn++) {
            int c = t0b + wn * 64 + tn * 8 + 2 * (lane & 3);
            #pragma unroll
            for (int half_ = 0; half_ < 2; half_++) {
                int m = m0b + wm * 32 + tm * 16 + (lane >> 2) + half_ * 8;
                __half2 v = __floats2half2_rn(acc[tm][tn][2 * half_ + 0] * 0.125f,
                                              acc[tm][tn][2 * half_ + 1] * 0.125f);
                *(__half2*)(Lb + (size_t)m * SEQ + c) = v;
            }
        }
    }
}

// ---------------------------------------------------------------------------
// K3: li = Q · pos_emb per (h,b) -> fp16
// ---------------------------------------------------------------------------
__global__ __launch_bounds__(256, 2) void qpe_mma()
{
    extern __shared__ char smem[];
    const int tid = threadIdx.x;
    const int warp = tid >> 5, lane = tid & 31;
    const int wm = warp >> 1, wn = warp & 1;
    const int n0b = blockIdx.x * 128, m0b = blockIdx.y * 128, hb = blockIdx.z;

    float acc[2][8][4] = {};
    mma_core<8>(gq + (size_t)hb * SEQ * HD + (size_t)m0b * HD, HD,
                gpet + (size_t)n0b * HD, HD,
                HD, acc, smem);

    __half* Lb = g_li + ((size_t)hb << 20);
    #pragma unroll
    for (int tm = 0; tm < 2; tm++) {
        #pragma unroll
        for (int tn = 0; tn < 8; tn++) {
            int c = n0b + wn * 64 + tn * 8 + 2 * (lane & 3);
            #pragma unroll
            for (int half_ = 0; half_ < 2; half_++) {
                int m = m0b + wm * 32 + tm * 16 + (lane >> 2) + half_ * 8;
                __half2 v = __floats2half2_rn(acc[tm][tn][2 * half_ + 0],
                                              acc[tm][tn][2 * half_ + 1]);
                *(__half2*)(Lb + (size_t)m * SEQ + c) = v;
            }
        }
    }
}

// ---------------------------------------------------------------------------
// K4: per-row CoPE + softmax; fp16 in / fp16 probs out, fp32 math inside.
// ---------------------------------------------------------------------------
__global__ __launch_bounds__(128) void cope_softmax()
{
    __shared__ __align__(16) float s_li[SEQ];
    __shared__ float s_w[4];
    __shared__ float s_m[4];
    __shared__ float s_s[4];

    const size_t row = blockIdx.x;
    __half* L = g_logits + (row << 10);
    const __half* li = g_li + (row << 10);
    const int tid = threadIdx.x;
    const int lane = tid & 31, warp = tid >> 5;

    {
        uint4 u = *(const uint4*)(li + tid * 8);
        const __half2* hp = (const __half2*)&u;
        #pragma unroll
        for (int i = 0; i < 4; i++) {
            float2 f = __half22float2(hp[i]);
            s_li[tid * 8 + 2 * i + 0] = f.x;
            s_li[tid * 8 + 2 * i + 1] = f.y;
        }
    }

    float l[8];
    {
        uint4 u = *(const uint4*)(L + tid * 8);
        const __half2* hp = (const __half2*)&u;
        #pragma unroll
        for (int i = 0; i < 4; i++) {
            float2 f = __half22float2(hp[i]);
            l[2 * i + 0] = f.x;
            l[2 * i + 1] = f.y;
        }
    }

    float su[8];
    {
        float g = sigmoidf_(l[7]); su[7] = g;
        #pragma unroll
        for (int j = 6; j >= 0; j--) su[j] = su[j + 1] + sigmoidf_(l[j]);
    }
    float total = su[0];

    float v = total;
    #pragma unroll
    for (int off = 1; off < 32; off <<= 1) {
        float n = __shfl_down_sync(0xffffffffu, v, off);
        if (lane + off < 32) v += n;
    }
    if (lane == 0) s_w[warp] = v;
    __syncthreads();

    float basew = 0.f;
    #pragma unroll
    for (int w = 0; w < 4; w++) if (w > warp) basew += s_w[w];
    float base = basew + (v - total);

    #pragma unroll
    for (int j = 0; j < 8; j++) {
        float p = fminf(base + su[j], 999.0f);
        float pf = floorf(p);
        float w = p - pf;
        int fi = (int)pf;
        int ci = (int)ceilf(p);
        l[j] += s_li[ci] * w + s_li[fi] * (1.0f - w);
    }

    float m = l[0];
    #pragma unroll
    for (int j = 1; j < 8; j++) m = fmaxf(m, l[j]);
    #pragma unroll
    for (int off = 16; off; off >>= 1)
        m = fmaxf(m, __shfl_xor_sync(0xffffffffu, m, off));
    if (lane == 0) s_m[warp] = m;
    __syncthreads();
    m = fmaxf(fmaxf(s_m[0], s_m[1]), fmaxf(s_m[2], s_m[3]));

    float sum = 0.f;
    #pragma unroll
    for (int j = 0; j < 8; j++) { l[j] = __expf(l[j] - m); sum += l[j]; }
    #pragma unroll
    for (int off = 16; off; off >>= 1)
        sum += __shfl_xor_sync(0xffffffffu, sum, off);
    if (lane == 0) s_s[warp] = sum;
    __syncthreads();
    float inv = 1.0f / (s_s[0] + s_s[1] + s_s[2] + s_s[3]);

    union { __half2 h2[4]; uint4 u; } pv;
    #pragma unroll
    for (int i = 0; i < 4; i++)
        pv.h2[i] = __floats2half2_rn(l[2 * i] * inv, l[2 * i + 1] * inv);
    *(uint4*)(gp + (row << 10) + tid * 8) = pv.u;
}

// ---------------------------------------------------------------------------
// K5: ctx = attn · V per (h,b). N = 64 -> fp16 ctx
// ---------------------------------------------------------------------------
__global__ __launch_bounds__(256, 2) void av_mma()
{
    extern __shared__ char smem[];
    const int tid = threadIdx.x;
    const int warp = tid >> 5, lane = tid & 31;
    const int wm = warp >> 1, wn = warp & 1;
    const int m0b = blockIdx.x * 128, hb = blockIdx.y;
    const int h = hb >> 2, b_ = hb & 3;

    float acc[2][4][4] = {};
    mma_core<4>(gp + ((size_t)hb << 20) + (size_t)m0b * SEQ, SEQ,
                gvt + (size_t)hb * HD * SEQ, SEQ,
                SEQ, acc, smem);

    #pragma unroll
    for (int tm = 0; tm < 2; tm++) {
        #pragma unroll
        for (int tn = 0; tn < 4; tn++) {
            int d = wn * 32 + tn * 8 + 2 * (lane & 3);
            #pragma unroll
            for (int half_ = 0; half_ < 2; half_++) {
                int s = m0b + wm * 32 + tm * 16 + (lane >> 2) + half_ * 8;
                __half2 v = __floats2half2_rn(acc[tm][tn][2 * half_ + 0],
                                              acc[tm][tn][2 * half_ + 1]);
                *(__half2*)(gctx + ((size_t)s * BATCH + b_) * DM + h * HD + d) = v;
            }
        }
    }
}

// ---------------------------------------------------------------------------
// K6: output projection (+bias) -> fp32 out
// ---------------------------------------------------------------------------
__global__ __launch_bounds__(256, 2) void out_mma(const float* __restrict__ bo,
                                                  float* __restrict__ out)
{
    extern __shared__ char smem[];
    const int tid = threadIdx.x;
    const int warp = tid >> 5, lane = tid & 31;
    const int wm = warp >> 1, wn = warp & 1;
    const int n0b = blockIdx.x * 128, m0b = blockIdx.y * 128;

    float acc[2][8][4] = {};
    mma_core<8>(gctx + (size_t)m0b * DM, DM,
                gw + (size_t)3 * DM * DM + (size_t)n0b * DM, DM,
                DM, acc, smem);

    #pragma unroll
    for (int tm = 0; tm < 2; tm++) {
        #pragma unroll
        for (int tn = 0; tn < 8; tn++) {
            int c = n0b + wn * 64 + tn * 8 + 2 * (lane & 3);
            float2 bb = *(const float2*)(bo + c);
            #pragma unroll
            for (int half_ = 0; half_ < 2; half_++) {
                int m = m0b + wm * 32 + tm * 16 + (lane >> 2) + half_ * 8;
                float2 v;
                v.x = acc[tm][tn][2 * half_ + 0] + bb.x;
                v.y = acc[tm][tn][2 * half_ + 1] + bb.y;
                *(float2*)(out + (size_t)m * DM + c) = v;
            }
        }
    }
}

// ---------------------------------------------------------------------------
extern "C" void kernel_launch(void* const* d_in, const int* in_sizes, int n_in,
                              void* d_out, int out_size)
{
    const float* x  = (const float*)d_in[0];
    const float* Wq = (const float*)d_in[1];
    const float* bq = (const float*)d_in[2];
    const float* Wk = (const float*)d_in[3];
    const float* bk = (const float*)d_in[4];
    const float* Wv = (const float*)d_in[5];
    const float* bv = (const float*)d_in[6];
    const float* Wo = (const float*)d_in[7];
    const float* bo = (const float*)d_in[8];
    const float* pe = (const float*)d_in[9];
    float* out = (float*)d_out;

    cudaFuncSetAttribute(qkv_mma, cudaFuncAttributeMaxDynamicSharedMemorySize, SMEM_N128);
    cudaFuncSetAttribute(qk_mma,  cudaFuncAttributeMaxDynamicSharedMemorySize, SMEM_N128);
    cudaFuncSetAttribute(qpe_mma, cudaFuncAttributeMaxDynamicSharedMemorySize, SMEM_N128);
    cudaFuncSetAttribute(out_mma, cudaFuncAttributeMaxDynamicSharedMemorySize, SMEM_N128);
    cudaFuncSetAttribute(av_mma,  cudaFuncAttributeMaxDynamicSharedMemorySize, SMEM_N64);

    convert_x<<<NTOK * DM / 1024, 256>>>(x);
    transpose_w<<<dim3(DM / 32, DM / 32, 4), 256>>>(Wq, Wk, Wv, Wo);
    transpose_pe<<<dim3(SEQ / 32, HD / 32), 256>>>(pe);

    qkv_mma<<<dim3(DM / 128, NTOK / 128, 3), 256, SMEM_N128>>>(bq, bk, bv);

    transpose_v<<<dim3(SEQ / 32, HD / 32, NHB), 256>>>();

    qk_mma<<<dim3(SEQ / 128, SEQ / 128, NHB), 256, SMEM_N128>>>();
    qpe_mma<<<dim3(SEQ / 128, SEQ / 128, NHB), 256, SMEM_N128>>>();

    cope_softmax<<<NHB * SEQ, 128>>>();

    av_mma<<<dim3(SEQ / 128, NHB), 256, SMEM_N64>>>();

    out_mma<<<dim3(DM / 128, NTOK / 128), 256, SMEM_N128>>>(bo, out);
}